// round 4
// baseline (speedup 1.0000x reference)
#include <cuda_runtime.h>

// ---------------- problem constants ----------------
#define Bc   4
#define Cc   256
#define Hc   256
#define Wc   256
#define HWc  65536
#define NHc  8
#define HDc  32
#define Pc   8
#define Gc   32
#define CPGc 8
#define NWIN 1024                       // 32*32 windows per batch
#define EPSc 1e-6f
#define ATTN_SCALE 0.17677669529663689f // 32^-0.5
#define RSQRT2c 0.70710678118654757f

typedef unsigned long long ull;

// ---------------- device scratch (no cudaMalloc allowed) ----------------
__device__ float g_mean[Bc * Gc];
__device__ float g_rstd[Bc * Gc];
__device__ float g_effw[(size_t)Bc * 768 * 256];   // per-batch GN-folded qkv weights
__device__ float g_effb[Bc * 768];
__device__ float g_qkv[(size_t)3 * Bc * Cc * HWc]; // [t][b][c][h][w]  (805 MB)
__device__ float g_att[(size_t)Bc * Cc * HWc];     // attention output (256 MB)

// ---------------- f32x2 helpers ----------------
__device__ __forceinline__ ull ffma2(ull a, ull b, ull c) {
    ull d;
    asm("fma.rn.f32x2 %0, %1, %2, %3;" : "=l"(d) : "l"(a), "l"(b), "l"(c));
    return d;
}
__device__ __forceinline__ ull dup2(float v) {
    ull r;
    asm("mov.b64 %0, {%1, %1};" : "=l"(r) : "f"(v));
    return r;
}
__device__ __forceinline__ ull pack2(float a, float b) {
    ull r;
    asm("mov.b64 %0, {%1, %2};" : "=l"(r) : "f"(a), "f"(b));
    return r;
}
__device__ __forceinline__ float2 unpack2(ull v) {
    float2 r;
    asm("mov.b64 {%0, %1}, %2;" : "=f"(r.x), "=f"(r.y) : "l"(v));
    return r;
}
union U4 { float4 f; ull u[2]; };

// ---------------- kernel 1: GroupNorm statistics ----------------
// One block per (b, g). Each group is a CONTIGUOUS 8*65536-float chunk.
__global__ __launch_bounds__(1024) void gn_stats_kernel(const float* __restrict__ x) {
    int bg = blockIdx.x; // b*32+g ; offset = bg * CPG*HW (channels contiguous)
    const float4* p = reinterpret_cast<const float4*>(x) + (size_t)bg * (CPGc * HWc / 4);
    float s = 0.f, ss = 0.f;
    const int n4 = CPGc * HWc / 4;
    for (int i = threadIdx.x; i < n4; i += blockDim.x) {
        float4 v = p[i];
        s  += (v.x + v.y) + (v.z + v.w);
        ss += (v.x * v.x + v.y * v.y) + (v.z * v.z + v.w * v.w);
    }
    const unsigned FULL = 0xffffffffu;
    #pragma unroll
    for (int o = 16; o; o >>= 1) {
        s  += __shfl_down_sync(FULL, s, o);
        ss += __shfl_down_sync(FULL, ss, o);
    }
    __shared__ float w1[32], w2[32];
    int lane = threadIdx.x & 31, wid = threadIdx.x >> 5;
    if (lane == 0) { w1[wid] = s; w2[wid] = ss; }
    __syncthreads();
    if (wid == 0) {
        int nw = blockDim.x >> 5;
        s  = (lane < nw) ? w1[lane] : 0.f;
        ss = (lane < nw) ? w2[lane] : 0.f;
        #pragma unroll
        for (int o = 16; o; o >>= 1) {
            s  += __shfl_down_sync(FULL, s, o);
            ss += __shfl_down_sync(FULL, ss, o);
        }
        if (lane == 0) {
            const float invN = 1.f / (float)(CPGc * HWc);
            float mu  = s * invN;
            float var = ss * invN - mu * mu;
            g_mean[bg] = mu;
            g_rstd[bg] = rsqrtf(var + EPSc);
        }
    }
}

// ---------------- kernel 2: fold GN into qkv weights ----------------
// block per (b, o) with o in [0,768). 256 threads = one weight row.
__global__ __launch_bounds__(256) void effw_kernel(
    const float* __restrict__ qw, const float* __restrict__ kw, const float* __restrict__ vw,
    const float* __restrict__ qb, const float* __restrict__ kb, const float* __restrict__ vb,
    const float* __restrict__ gnw, const float* __restrict__ gnb)
{
    int bo = blockIdx.x;
    int b = bo / 768, o = bo % 768;
    int t = o >> 8, oc = o & 255;
    const float* Wm   = (t == 0) ? qw : ((t == 1) ? kw : vw);
    const float* bias = (t == 0) ? qb : ((t == 1) ? kb : vb);
    int c = threadIdx.x;
    float w  = Wm[oc * 256 + c];
    int g    = c >> 3;
    float rs = g_rstd[b * Gc + g];
    float mu = g_mean[b * Gc + g];
    float sC = rs * gnw[c];
    float tC = gnb[c] - mu * sC;
    g_effw[(size_t)bo * 256 + c] = w * sC;

    float v = w * tC;
    const unsigned FULL = 0xffffffffu;
    #pragma unroll
    for (int off = 16; off; off >>= 1) v += __shfl_down_sync(FULL, v, off);
    __shared__ float ws[8];
    int lane = c & 31, wid = c >> 5;
    if (lane == 0) ws[wid] = v;
    __syncthreads();
    if (c == 0) {
        float sum = 0.f;
        #pragma unroll
        for (int i = 0; i < 8; i++) sum += ws[i];
        g_effb[bo] = sum + bias[oc];
    }
}

// ---------------- kernels 3 & 5: tiled SGEMM (f32x2) ----------------
// C[m][n] = sum_k A[k][m] * W[n][k] (+bias [+resid, *1/sqrt2])
// A is (K, M) with M contiguous (i.e. (B,C,H,W) channel-major layout).
#define BM 128
#define BN 64
#define BK 16

template <bool OCONV>
__global__ __launch_bounds__(256) void gemm_kernel(
    const float* __restrict__ Abase,   // QKV: input x ; OCONV: unused (g_att)
    const float* __restrict__ Wbase,   // OCONV: o_w ; QKV: unused (g_effw)
    const float* __restrict__ biasbase,// OCONV: o_b ; QKV: unused (g_effb)
    const float* __restrict__ resid,   // OCONV: x
    float* __restrict__ outbase)       // OCONV: d_out ; QKV: unused (g_qkv)
{
    __shared__ float As[2][BK][BM];
    __shared__ float Bs[2][BK][BN + 4];

    const int b     = blockIdx.z;
    const size_t mbase = (size_t)blockIdx.x * BM;
    const int nbase = blockIdx.y * BN;

    const float* A = (OCONV ? (const float*)g_att : Abase) + (size_t)b * Cc * HWc + mbase;
    const float* Bw = OCONV ? (Wbase + (size_t)nbase * Cc)
                            : (&g_effw[((size_t)b * 768 + nbase) * Cc]);

    const int tid  = threadIdx.x;
    const int la_k = tid >> 5;         // 0..7
    const int la_m = (tid & 31) << 2;  // 0..124
    const int lb_n = tid >> 2;         // 0..63
    const int lb_k = (tid & 3) << 2;   // 0,4,8,12
    const int mt   = tid & 15;
    const int nt   = tid >> 4;
    const int m0   = mt << 2;          // + split half at +64
    const int n0   = nt << 2;

    ull acc[4][4];
    #pragma unroll
    for (int i = 0; i < 4; i++)
        #pragma unroll
        for (int j = 0; j < 4; j++) acc[i][j] = 0ull;

    float4 ra0, ra1, rb;
    // prologue: tile 0
    ra0 = *(const float4*)(A + (size_t)la_k * HWc + la_m);
    ra1 = *(const float4*)(A + (size_t)(la_k + 8) * HWc + la_m);
    rb  = *(const float4*)(Bw + (size_t)lb_n * Cc + lb_k);
    *(float4*)&As[0][la_k][la_m]     = ra0;
    *(float4*)&As[0][la_k + 8][la_m] = ra1;
    Bs[0][lb_k + 0][lb_n] = rb.x;
    Bs[0][lb_k + 1][lb_n] = rb.y;
    Bs[0][lb_k + 2][lb_n] = rb.z;
    Bs[0][lb_k + 3][lb_n] = rb.w;
    __syncthreads();

    const int NK = Cc / BK; // 16
    for (int kt = 0; kt < NK; kt++) {
        const int cur = kt & 1;
        if (kt + 1 < NK) {
            const float* Ak = A + (size_t)(kt + 1) * BK * HWc;
            ra0 = *(const float4*)(Ak + (size_t)la_k * HWc + la_m);
            ra1 = *(const float4*)(Ak + (size_t)(la_k + 8) * HWc + la_m);
            rb  = *(const float4*)(Bw + (size_t)lb_n * Cc + (kt + 1) * BK + lb_k);
        }
        #pragma unroll
        for (int k = 0; k < BK; k++) {
            U4 a0; a0.f = *(const float4*)&As[cur][k][m0];
            U4 a1; a1.f = *(const float4*)&As[cur][k][64 + m0];
            float4 bv = *(const float4*)&Bs[cur][k][n0];
            float barr[4] = {bv.x, bv.y, bv.z, bv.w};
            #pragma unroll
            for (int nn = 0; nn < 4; nn++) {
                ull bd = dup2(barr[nn]);
                acc[nn][0] = ffma2(a0.u[0], bd, acc[nn][0]);
                acc[nn][1] = ffma2(a0.u[1], bd, acc[nn][1]);
                acc[nn][2] = ffma2(a1.u[0], bd, acc[nn][2]);
                acc[nn][3] = ffma2(a1.u[1], bd, acc[nn][3]);
            }
        }
        if (kt + 1 < NK) {
            const int nxt = cur ^ 1;
            *(float4*)&As[nxt][la_k][la_m]     = ra0;
            *(float4*)&As[nxt][la_k + 8][la_m] = ra1;
            Bs[nxt][lb_k + 0][lb_n] = rb.x;
            Bs[nxt][lb_k + 1][lb_n] = rb.y;
            Bs[nxt][lb_k + 2][lb_n] = rb.z;
            Bs[nxt][lb_k + 3][lb_n] = rb.w;
            __syncthreads();
        }
    }

    // epilogue
    #pragma unroll
    for (int nn = 0; nn < 4; nn++) {
        const int o = nbase + n0 + nn;
        float bv = OCONV ? biasbase[o] : g_effb[b * 768 + o];
        float2 c0 = unpack2(acc[nn][0]);
        float2 c1 = unpack2(acc[nn][1]);
        float2 c2 = unpack2(acc[nn][2]);
        float2 c3 = unpack2(acc[nn][3]);
        if (OCONV) {
            size_t ro = ((size_t)b * Cc + o) * HWc + mbase;
            const float* qr = resid + ro;
            float* op = outbase + ro;
            float4 w0, w1;
            w0.x = (c0.x + bv + qr[m0 + 0]) * RSQRT2c;
            w0.y = (c0.y + bv + qr[m0 + 1]) * RSQRT2c;
            w0.z = (c1.x + bv + qr[m0 + 2]) * RSQRT2c;
            w0.w = (c1.y + bv + qr[m0 + 3]) * RSQRT2c;
            w1.x = (c2.x + bv + qr[64 + m0 + 0]) * RSQRT2c;
            w1.y = (c2.y + bv + qr[64 + m0 + 1]) * RSQRT2c;
            w1.z = (c3.x + bv + qr[64 + m0 + 2]) * RSQRT2c;
            w1.w = (c3.y + bv + qr[64 + m0 + 3]) * RSQRT2c;
            *(float4*)(op + m0)      = w0;
            *(float4*)(op + 64 + m0) = w1;
        } else {
            int t = o >> 8, cch = o & 255;
            float* op = g_qkv + (((size_t)t * Bc + b) * Cc + cch) * HWc + mbase;
            float4 w0 = {c0.x + bv, c0.y + bv, c1.x + bv, c1.y + bv};
            float4 w1 = {c2.x + bv, c2.y + bv, c3.x + bv, c3.y + bv};
            *(float4*)(op + m0)      = w0;
            *(float4*)(op + 64 + m0) = w1;
        }
    }
}

// ---------------- kernel 4: windowed attention ----------------
// block per (window, head, batch); 64 threads, one S-row per thread.
__global__ __launch_bounds__(64) void attn_kernel() {
    const int win = blockIdx.x, head = blockIdx.y, b = blockIdx.z;
    const int hpi = win >> 5, wpi = win & 31;

    __shared__ float qs[HDc][68];  // [hd][token], row stride 272B (16B aligned)
    __shared__ float ks[HDc][68];
    __shared__ float vs[64][36];   // [token][hd], row stride 144B (16B aligned)

    const int tid = threadIdx.x;
    const size_t TSTR = (size_t)Bc * Cc * HWc;
    const size_t base = ((size_t)b * Cc + head * HDc) * HWc
                      + (size_t)(hpi * Pc) * Wc + wpi * Pc;
    const float* qg = g_qkv + base;
    const float* kg = g_qkv + TSTR + base;
    const float* vg = g_qkv + 2 * TSTR + base;

    #pragma unroll
    for (int it = 0; it < 32; it++) {
        int i = tid + it * 64;
        int hd = i >> 6, tok = i & 63;
        size_t off = (size_t)hd * HWc + (size_t)(tok >> 3) * Wc + (tok & 7);
        qs[hd][tok] = qg[off];
        ks[hd][tok] = kg[off];
        vs[tok][hd] = vg[off];
    }
    __syncthreads();

    const int i = tid; // my query row (token)
    ull s2[32];
    #pragma unroll
    for (int jp = 0; jp < 32; jp++) s2[jp] = 0ull;

    // S[i][j] = sum_hd q[hd][i] * k[hd][j]
    #pragma unroll 8
    for (int hd = 0; hd < HDc; hd++) {
        ull q2 = dup2(qs[hd][i]);
        const float4* kr = reinterpret_cast<const float4*>(&ks[hd][0]);
        #pragma unroll
        for (int jq = 0; jq < 16; jq++) {
            U4 u; u.f = kr[jq];
            s2[jq * 2]     = ffma2(u.u[0], q2, s2[jq * 2]);
            s2[jq * 2 + 1] = ffma2(u.u[1], q2, s2[jq * 2 + 1]);
        }
    }

    // softmax over j (whole row is local to this thread)
    float mx = -3.0e38f;
    #pragma unroll
    for (int jp = 0; jp < 32; jp++) {
        float2 v = unpack2(s2[jp]);
        mx = fmaxf(mx, fmaxf(v.x, v.y));
    }
    float ssum = 0.f;
    #pragma unroll
    for (int jp = 0; jp < 32; jp++) {
        float2 v = unpack2(s2[jp]);
        float ea = __expf((v.x - mx) * ATTN_SCALE);
        float eb = __expf((v.y - mx) * ATTN_SCALE);
        ssum += ea + eb;
        s2[jp] = pack2(ea, eb);
    }
    const float inv = 1.f / ssum;

    // O[i][hd] = (1/sum) * sum_j P[i][j] * V[j][hd]
    ull o2[16];
    #pragma unroll
    for (int hp = 0; hp < 16; hp++) o2[hp] = 0ull;
    #pragma unroll
    for (int jp = 0; jp < 32; jp++) {
        float2 pv = unpack2(s2[jp]);
        ull pa = dup2(pv.x), pb = dup2(pv.y);
        const float4* va = reinterpret_cast<const float4*>(&vs[jp * 2][0]);
        const float4* vb = reinterpret_cast<const float4*>(&vs[jp * 2 + 1][0]);
        #pragma unroll
        for (int hq = 0; hq < 8; hq++) {
            U4 ua; ua.f = va[hq];
            U4 ub; ub.f = vb[hq];
            o2[hq * 2]     = ffma2(ua.u[0], pa, o2[hq * 2]);
            o2[hq * 2 + 1] = ffma2(ua.u[1], pa, o2[hq * 2 + 1]);
            o2[hq * 2]     = ffma2(ub.u[0], pb, o2[hq * 2]);
            o2[hq * 2 + 1] = ffma2(ub.u[1], pb, o2[hq * 2 + 1]);
        }
    }

    const size_t obase = ((size_t)b * Cc + head * HDc) * HWc
                       + (size_t)(hpi * Pc + (i >> 3)) * Wc + wpi * Pc + (i & 7);
    #pragma unroll
    for (int hp = 0; hp < 16; hp++) {
        float2 v = unpack2(o2[hp]);
        g_att[obase + (size_t)(2 * hp) * HWc]     = v.x * inv;
        g_att[obase + (size_t)(2 * hp + 1) * HWc] = v.y * inv;
    }
}

// ---------------- launch ----------------
extern "C" void kernel_launch(void* const* d_in, const int* in_sizes, int n_in,
                              void* d_out, int out_size) {
    const float* x    = (const float*)d_in[0];
    const float* gn_w = (const float*)d_in[1];
    const float* gn_b = (const float*)d_in[2];
    const float* q_w  = (const float*)d_in[3];
    const float* q_b  = (const float*)d_in[4];
    const float* k_w  = (const float*)d_in[5];
    const float* k_b  = (const float*)d_in[6];
    const float* v_w  = (const float*)d_in[7];
    const float* v_b  = (const float*)d_in[8];
    const float* o_w  = (const float*)d_in[9];
    const float* o_b  = (const float*)d_in[10];
    float* out = (float*)d_out;

    gn_stats_kernel<<<Bc * Gc, 1024>>>(x);
    effw_kernel<<<Bc * 768, 256>>>(q_w, k_w, v_w, q_b, k_b, v_b, gn_w, gn_b);

    dim3 gq(HWc / BM, 768 / BN, Bc);
    gemm_kernel<false><<<gq, 256>>>(x, nullptr, nullptr, nullptr, nullptr);

    dim3 ga(NWIN, NHc, Bc);
    attn_kernel<<<ga, 64>>>();

    dim3 go(HWc / BM, Cc / BN, Bc);
    gemm_kernel<true><<<go, 256>>>(nullptr, o_w, o_b, x, out);
}

// round 6
// speedup vs baseline: 1.8492x; 1.8492x over previous
#include <cuda_runtime.h>
#include <cstdint>

// ---------------- problem constants ----------------
#define Bc   4
#define Cc   256
#define Hc   256
#define Wc   256
#define HWc  65536
#define NHc  8
#define HDc  32
#define Pc   8
#define Gc   32
#define CPGc 8
#define NWIN 1024
#define EPSc 1e-6f
#define ATTN_SCALE 0.17677669529663689f
#define RSQRT2c 0.70710678118654757f

typedef unsigned long long ull;

// ---------------- device scratch (no cudaMalloc allowed) ----------------
__device__ float g_mean[Bc * Gc];
__device__ float g_rstd[Bc * Gc];
__device__ float g_effw[(size_t)Bc * 768 * 256];   // GN-folded qkv weights (tf32-rounded)
__device__ float g_effb[Bc * 768];                 // folded bias (fp32)
__device__ float g_owr[256 * 256];                 // o_w tf32-rounded
__device__ float g_xr[(size_t)Bc * Cc * HWc];      // x tf32-rounded (256 MB)
__device__ float g_qkv[(size_t)3 * Bc * Cc * HWc]; // [t][b][c][h][w]  (805 MB)
__device__ float g_att[(size_t)Bc * Cc * HWc];     // attention out, tf32-rounded (256 MB)

// ---------------- helpers ----------------
__device__ __forceinline__ float rna_tf32(float x) {
    uint32_t r;
    asm("cvt.rna.tf32.f32 %0, %1;" : "=r"(r) : "f"(x));
    return __uint_as_float(r);
}
__device__ __forceinline__ uint32_t smem_u32(const void* p) {
    uint32_t a;
    asm("{ .reg .u64 t; cvta.to.shared.u64 t, %1; cvt.u32.u64 %0, t; }" : "=r"(a) : "l"(p));
    return a;
}
__device__ __forceinline__ void cpasync16(uint32_t dst, const void* src) {
    asm volatile("cp.async.cg.shared.global [%0], [%1], 16;" :: "r"(dst), "l"(src) : "memory");
}
__device__ __forceinline__ void mma1688(float* d, const uint32_t* a, uint32_t b0, uint32_t b1) {
    asm volatile(
        "mma.sync.aligned.m16n8k8.row.col.f32.tf32.tf32.f32 "
        "{%0,%1,%2,%3}, {%4,%5,%6,%7}, {%8,%9}, {%0,%1,%2,%3};"
        : "+f"(d[0]), "+f"(d[1]), "+f"(d[2]), "+f"(d[3])
        : "r"(a[0]), "r"(a[1]), "r"(a[2]), "r"(a[3]), "r"(b0), "r"(b1));
}

// f32x2 helpers (attention)
__device__ __forceinline__ ull ffma2(ull a, ull b, ull c) {
    ull d; asm("fma.rn.f32x2 %0, %1, %2, %3;" : "=l"(d) : "l"(a), "l"(b), "l"(c)); return d;
}
__device__ __forceinline__ ull dup2(float v) {
    ull r; asm("mov.b64 %0, {%1, %1};" : "=l"(r) : "f"(v)); return r;
}
__device__ __forceinline__ ull pack2(float a, float b) {
    ull r; asm("mov.b64 %0, {%1, %2};" : "=l"(r) : "f"(a), "f"(b)); return r;
}
__device__ __forceinline__ float2 unpack2(ull v) {
    float2 r; asm("mov.b64 {%0, %1}, %2;" : "=f"(r.x), "=f"(r.y) : "l"(v)); return r;
}
union U4 { float4 f; ull u[2]; };

// ---------------- kernel 1: GroupNorm statistics ----------------
__global__ __launch_bounds__(1024) void gn_stats_kernel(const float* __restrict__ x) {
    int bg = blockIdx.x;
    const float4* p = reinterpret_cast<const float4*>(x) + (size_t)bg * (CPGc * HWc / 4);
    float s = 0.f, ss = 0.f;
    const int n4 = CPGc * HWc / 4;
    for (int i = threadIdx.x; i < n4; i += blockDim.x) {
        float4 v = p[i];
        s  += (v.x + v.y) + (v.z + v.w);
        ss += (v.x * v.x + v.y * v.y) + (v.z * v.z + v.w * v.w);
    }
    const unsigned FULL = 0xffffffffu;
    #pragma unroll
    for (int o = 16; o; o >>= 1) { s += __shfl_down_sync(FULL, s, o); ss += __shfl_down_sync(FULL, ss, o); }
    __shared__ float w1[32], w2[32];
    int lane = threadIdx.x & 31, wid = threadIdx.x >> 5;
    if (lane == 0) { w1[wid] = s; w2[wid] = ss; }
    __syncthreads();
    if (wid == 0) {
        int nw = blockDim.x >> 5;
        s  = (lane < nw) ? w1[lane] : 0.f;
        ss = (lane < nw) ? w2[lane] : 0.f;
        #pragma unroll
        for (int o = 16; o; o >>= 1) { s += __shfl_down_sync(FULL, s, o); ss += __shfl_down_sync(FULL, ss, o); }
        if (lane == 0) {
            const float invN = 1.f / (float)(CPGc * HWc);
            float mu  = s * invN;
            float var = ss * invN - mu * mu;
            g_mean[bg] = mu;
            g_rstd[bg] = rsqrtf(var + EPSc);
        }
    }
}

// ---------------- kernel 2: fold GN into qkv weights (tf32-rounded) ----------------
__global__ __launch_bounds__(256) void effw_kernel(
    const float* __restrict__ qw, const float* __restrict__ kw, const float* __restrict__ vw,
    const float* __restrict__ qb, const float* __restrict__ kb, const float* __restrict__ vb,
    const float* __restrict__ gnw, const float* __restrict__ gnb)
{
    int bo = blockIdx.x;
    int b = bo / 768, o = bo % 768;
    int t = o >> 8, oc = o & 255;
    const float* Wm   = (t == 0) ? qw : ((t == 1) ? kw : vw);
    const float* bias = (t == 0) ? qb : ((t == 1) ? kb : vb);
    int c = threadIdx.x;
    float w  = Wm[oc * 256 + c];
    int g    = c >> 3;
    float rs = g_rstd[b * Gc + g];
    float mu = g_mean[b * Gc + g];
    float sC = rs * gnw[c];
    float tC = gnb[c] - mu * sC;
    g_effw[(size_t)bo * 256 + c] = rna_tf32(w * sC);

    float v = w * tC;
    const unsigned FULL = 0xffffffffu;
    #pragma unroll
    for (int off = 16; off; off >>= 1) v += __shfl_down_sync(FULL, v, off);
    __shared__ float ws[8];
    int lane = c & 31, wid = c >> 5;
    if (lane == 0) ws[wid] = v;
    __syncthreads();
    if (c == 0) {
        float sum = 0.f;
        #pragma unroll
        for (int i = 0; i < 8; i++) sum += ws[i];
        g_effb[bo] = sum + bias[oc];
    }
}

// ---------------- pre-rounding passes ----------------
__global__ __launch_bounds__(256) void round_x_kernel(const float* __restrict__ x) {
    const size_t n4 = (size_t)Bc * Cc * HWc / 4;
    const size_t stride = (size_t)gridDim.x * blockDim.x;
    const float4* src = (const float4*)x;
    float4* dst = (float4*)g_xr;
    for (size_t j = (size_t)blockIdx.x * blockDim.x + threadIdx.x; j < n4; j += stride) {
        float4 v = src[j];
        v.x = rna_tf32(v.x); v.y = rna_tf32(v.y);
        v.z = rna_tf32(v.z); v.w = rna_tf32(v.w);
        dst[j] = v;
    }
}
__global__ __launch_bounds__(256) void round_ow_kernel(const float* __restrict__ ow) {
    int j = blockIdx.x * blockDim.x + threadIdx.x; // 16384 float4s
    float4 v = ((const float4*)ow)[j];
    v.x = rna_tf32(v.x); v.y = rna_tf32(v.y);
    v.z = rna_tf32(v.z); v.w = rna_tf32(v.w);
    ((float4*)g_owr)[j] = v;
}

// ---------------- kernels 3 & 5: tf32 mma.sync GEMM ----------------
// C[n][m] = sum_k A[k][m] * W[n][k]  (A m-contiguous), CTA tile 128m x 256n, BK=16.
// 8 warps: warp_m = wid&1 (2), warp_n = wid>>1 (4); warp tile 64x64.
// smem floats: A[3][16][136] at 0 (2176/stage), B[3][256][20] at 6528 (5120/stage).
#define SM_TOTAL_B 87552
#define NKI 16

template <bool OCONV>
__global__ void __launch_bounds__(256)
mma_gemm_kernel(const float* __restrict__ biasin, const float* __restrict__ resid,
                float* __restrict__ outp)
{
    extern __shared__ float sm[];
    const uint32_t sbase = smem_u32(sm);
    const int tid = threadIdx.x, lane = tid & 31, wid = tid >> 5;
    const int warp_m = wid & 1, warp_n = wid >> 1;
    const int ny = blockIdx.x;
    const size_t mbase = (size_t)blockIdx.y * 128;
    const int b = blockIdx.z;

    const float* Ag = (OCONV ? g_att : g_xr) + (size_t)b * Cc * HWc + mbase;
    const float* Wg = OCONV ? g_owr : (g_effw + ((size_t)b * 768 + ny * 256) * 256);

    float acc[4][8][4];
    #pragma unroll
    for (int i = 0; i < 4; i++)
        #pragma unroll
        for (int j = 0; j < 8; j++)
            #pragma unroll
            for (int l = 0; l < 4; l++) acc[i][j][l] = 0.f;

    auto issue = [&](int kt, int s) {
        const float* Asrc = Ag + (size_t)kt * 16 * HWc;
        uint32_t Ad = sbase + (uint32_t)(s * 2176) * 4u;
        #pragma unroll
        for (int it = 0; it < 2; it++) {
            int lin = it * 256 + tid;
            int k = lin >> 5, m4 = (lin & 31) << 2;
            cpasync16(Ad + (uint32_t)(k * 136 + m4) * 4u, Asrc + (size_t)k * HWc + m4);
        }
        const float* Bsrc = Wg + kt * 16;
        uint32_t Bd = sbase + (uint32_t)(6528 + s * 5120) * 4u;
        #pragma unroll
        for (int it = 0; it < 4; it++) {
            int lin = it * 256 + tid;
            int n = lin >> 2, k4 = (lin & 3) << 2;
            cpasync16(Bd + (uint32_t)(n * 20 + k4) * 4u, Bsrc + (size_t)n * 256 + k4);
        }
        asm volatile("cp.async.commit_group;" ::: "memory");
    };

    issue(0, 0);
    issue(1, 1);

    const int r = lane >> 2, c = lane & 3;
    #pragma unroll 1
    for (int kt = 0; kt < NKI; kt++) {
        const int cur = kt % 3;
        if (kt + 2 < NKI) issue(kt + 2, (kt + 2) % 3);
        if (kt < NKI - 2)      asm volatile("cp.async.wait_group 2;" ::: "memory");
        else if (kt == NKI - 2) asm volatile("cp.async.wait_group 1;" ::: "memory");
        else                   asm volatile("cp.async.wait_group 0;" ::: "memory");
        __syncthreads();

        const float* As = sm + cur * 2176;
        const float* Bs = sm + 6528 + cur * 5120;
        #pragma unroll
        for (int ks = 0; ks < 2; ks++) {
            const int kb = ks * 8;
            uint32_t af[4][4];
            #pragma unroll
            for (int mt = 0; mt < 4; mt++) {
                int m = warp_m * 64 + mt * 16 + r;
                af[mt][0] = __float_as_uint(As[(kb + c) * 136 + m]);
                af[mt][1] = __float_as_uint(As[(kb + c) * 136 + m + 8]);
                af[mt][2] = __float_as_uint(As[(kb + c + 4) * 136 + m]);
                af[mt][3] = __float_as_uint(As[(kb + c + 4) * 136 + m + 8]);
            }
            #pragma unroll
            for (int nt = 0; nt < 8; nt++) {
                int n = warp_n * 64 + nt * 8 + r;
                uint32_t b0 = __float_as_uint(Bs[n * 20 + kb + c]);
                uint32_t b1 = __float_as_uint(Bs[n * 20 + kb + c + 4]);
                #pragma unroll
                for (int mt = 0; mt < 4; mt++) mma1688(acc[mt][nt], af[mt], b0, b1);
            }
        }
        __syncthreads();
    }

    // ---------------- epilogue ----------------
    const float* bptr = OCONV ? biasin : (g_effb + b * 768 + ny * 256);
    #pragma unroll
    for (int nt = 0; nt < 8; nt++) {
        int nloc = warp_n * 64 + nt * 8 + 2 * (lane & 3);
        float b0v = bptr[nloc], b1v = bptr[nloc + 1];
        #pragma unroll
        for (int mt = 0; mt < 4; mt++) {
            size_t mg = mbase + warp_m * 64 + mt * 16 + (lane >> 2);
            if (OCONV) {
                size_t o0 = ((size_t)b * Cc + nloc) * HWc + mg;
                size_t o1 = o0 + HWc;
                outp[o0]     = (acc[mt][nt][0] + b0v + resid[o0]) * RSQRT2c;
                outp[o1]     = (acc[mt][nt][1] + b1v + resid[o1]) * RSQRT2c;
                outp[o0 + 8] = (acc[mt][nt][2] + b0v + resid[o0 + 8]) * RSQRT2c;
                outp[o1 + 8] = (acc[mt][nt][3] + b1v + resid[o1 + 8]) * RSQRT2c;
            } else {
                size_t o0 = ((size_t)(ny * Bc + b) * Cc + nloc) * HWc + mg;
                size_t o1 = o0 + HWc;
                g_qkv[o0]     = acc[mt][nt][0] + b0v;
                g_qkv[o1]     = acc[mt][nt][1] + b1v;
                g_qkv[o0 + 8] = acc[mt][nt][2] + b0v;
                g_qkv[o1 + 8] = acc[mt][nt][3] + b1v;
            }
        }
    }
}

// ---------------- kernel 4: windowed attention ----------------
__global__ __launch_bounds__(64) void attn_kernel() {
    const int win = blockIdx.x, head = blockIdx.y, b = blockIdx.z;
    const int hpi = win >> 5, wpi = win & 31;

    __shared__ float qs[HDc][68];
    __shared__ float ks[HDc][68];
    __shared__ float vs[64][36];

    const int tid = threadIdx.x;
    const size_t TSTR = (size_t)Bc * Cc * HWc;
    const size_t base = ((size_t)b * Cc + head * HDc) * HWc
                      + (size_t)(hpi * Pc) * Wc + wpi * Pc;
    const float* qg = g_qkv + base;
    const float* kg = g_qkv + TSTR + base;
    const float* vg = g_qkv + 2 * TSTR + base;

    #pragma unroll
    for (int it = 0; it < 32; it++) {
        int i = tid + it * 64;
        int hd = i >> 6, tok = i & 63;
        size_t off = (size_t)hd * HWc + (size_t)(tok >> 3) * Wc + (tok & 7);
        qs[hd][tok] = qg[off];
        ks[hd][tok] = kg[off];
        vs[tok][hd] = vg[off];
    }
    __syncthreads();

    const int i = tid;
    ull s2[32];
    #pragma unroll
    for (int jp = 0; jp < 32; jp++) s2[jp] = 0ull;

    #pragma unroll 8
    for (int hd = 0; hd < HDc; hd++) {
        ull q2 = dup2(qs[hd][i]);
        const float4* kr = reinterpret_cast<const float4*>(&ks[hd][0]);
        #pragma unroll
        for (int jq = 0; jq < 16; jq++) {
            U4 u; u.f = kr[jq];
            s2[jq * 2]     = ffma2(u.u[0], q2, s2[jq * 2]);
            s2[jq * 2 + 1] = ffma2(u.u[1], q2, s2[jq * 2 + 1]);
        }
    }

    float mx = -3.0e38f;
    #pragma unroll
    for (int jp = 0; jp < 32; jp++) {
        float2 v = unpack2(s2[jp]);
        mx = fmaxf(mx, fmaxf(v.x, v.y));
    }
    float ssum = 0.f;
    #pragma unroll
    for (int jp = 0; jp < 32; jp++) {
        float2 v = unpack2(s2[jp]);
        float ea = __expf((v.x - mx) * ATTN_SCALE);
        float eb = __expf((v.y - mx) * ATTN_SCALE);
        ssum += ea + eb;
        s2[jp] = pack2(ea, eb);
    }
    const float inv = 1.f / ssum;

    ull o2[16];
    #pragma unroll
    for (int hp = 0; hp < 16; hp++) o2[hp] = 0ull;
    #pragma unroll
    for (int jp = 0; jp < 32; jp++) {
        float2 pv = unpack2(s2[jp]);
        ull pa = dup2(pv.x), pb = dup2(pv.y);
        const float4* va = reinterpret_cast<const float4*>(&vs[jp * 2][0]);
        const float4* vb = reinterpret_cast<const float4*>(&vs[jp * 2 + 1][0]);
        #pragma unroll
        for (int hq = 0; hq < 8; hq++) {
            U4 ua; ua.f = va[hq];
            U4 ub; ub.f = vb[hq];
            o2[hq * 2]     = ffma2(ua.u[0], pa, o2[hq * 2]);
            o2[hq * 2 + 1] = ffma2(ua.u[1], pa, o2[hq * 2 + 1]);
            o2[hq * 2]     = ffma2(ub.u[0], pb, o2[hq * 2]);
            o2[hq * 2 + 1] = ffma2(ub.u[1], pb, o2[hq * 2 + 1]);
        }
    }

    const size_t obase = ((size_t)b * Cc + head * HDc) * HWc
                       + (size_t)(hpi * Pc + (i >> 3)) * Wc + wpi * Pc + (i & 7);
    #pragma unroll
    for (int hp = 0; hp < 16; hp++) {
        float2 v = unpack2(o2[hp]);
        g_att[obase + (size_t)(2 * hp) * HWc]     = rna_tf32(v.x * inv);
        g_att[obase + (size_t)(2 * hp + 1) * HWc] = rna_tf32(v.y * inv);
    }
}

// ---------------- launch ----------------
extern "C" void kernel_launch(void* const* d_in, const int* in_sizes, int n_in,
                              void* d_out, int out_size) {
    const float* x    = (const float*)d_in[0];
    const float* gn_w = (const float*)d_in[1];
    const float* gn_b = (const float*)d_in[2];
    const float* q_w  = (const float*)d_in[3];
    const float* q_b  = (const float*)d_in[4];
    const float* k_w  = (const float*)d_in[5];
    const float* k_b  = (const float*)d_in[6];
    const float* v_w  = (const float*)d_in[7];
    const float* v_b  = (const float*)d_in[8];
    const float* o_w  = (const float*)d_in[9];
    const float* o_b  = (const float*)d_in[10];
    float* out = (float*)d_out;

    cudaFuncSetAttribute(mma_gemm_kernel<false>,
                         cudaFuncAttributeMaxDynamicSharedMemorySize, SM_TOTAL_B);
    cudaFuncSetAttribute(mma_gemm_kernel<true>,
                         cudaFuncAttributeMaxDynamicSharedMemorySize, SM_TOTAL_B);

    gn_stats_kernel<<<Bc * Gc, 1024>>>(x);
    effw_kernel<<<Bc * 768, 256>>>(q_w, k_w, v_w, q_b, k_b, v_b, gn_w, gn_b);
    round_x_kernel<<<8192, 256>>>(x);
    round_ow_kernel<<<64, 256>>>(o_w);

    dim3 gq(3, HWc / 128, Bc);
    mma_gemm_kernel<false><<<gq, 256, SM_TOTAL_B>>>(nullptr, nullptr, nullptr);

    dim3 ga(NWIN, NHc, Bc);
    attn_kernel<<<ga, 64>>>();

    dim3 go(1, HWc / 128, Bc);
    mma_gemm_kernel<true><<<go, 256, SM_TOTAL_B>>>(o_b, x, out);
}

// round 7
// speedup vs baseline: 2.1529x; 1.1642x over previous
#include <cuda_runtime.h>
#include <cstdint>

// ---------------- problem constants ----------------
#define Bc   4
#define Cc   256
#define Hc   256
#define Wc   256
#define HWc  65536
#define NHc  8
#define HDc  32
#define Pc   8
#define Gc   32
#define CPGc 8
#define NWIN 1024
#define EPSc 1e-6f
#define ATTN_SCALE 0.17677669529663689f
#define RSQRT2c 0.70710678118654757f

typedef unsigned long long ull;

// ---------------- device scratch (no cudaMalloc allowed) ----------------
__device__ float g_mean[Bc * Gc];
__device__ float g_rstd[Bc * Gc];
__device__ float g_effw[(size_t)Bc * 768 * 256];   // GN-folded qkv weights (tf32-rounded)
__device__ float g_effb[Bc * 768];                 // folded bias (fp32)
__device__ float g_owr[256 * 256];                 // o_w tf32-rounded
__device__ float g_xr[(size_t)Bc * Cc * HWc];      // x tf32-rounded (256 MB)
__device__ float g_qkv[(size_t)3 * Bc * Cc * HWc]; // [t][b][c][h][w]  (805 MB)
__device__ float g_att[(size_t)Bc * Cc * HWc];     // attention out, tf32-rounded (256 MB)

// ---------------- helpers ----------------
__device__ __forceinline__ float rna_tf32(float x) {
    uint32_t r;
    asm("cvt.rna.tf32.f32 %0, %1;" : "=r"(r) : "f"(x));
    return __uint_as_float(r);
}
__device__ __forceinline__ uint32_t smem_u32(const void* p) {
    uint32_t a;
    asm("{ .reg .u64 t; cvta.to.shared.u64 t, %1; cvt.u32.u64 %0, t; }" : "=r"(a) : "l"(p));
    return a;
}
__device__ __forceinline__ void cpasync16(uint32_t dst, const void* src) {
    asm volatile("cp.async.cg.shared.global [%0], [%1], 16;" :: "r"(dst), "l"(src) : "memory");
}
__device__ __forceinline__ void mma1688(float* d, const uint32_t* a, uint32_t b0, uint32_t b1) {
    asm volatile(
        "mma.sync.aligned.m16n8k8.row.col.f32.tf32.tf32.f32 "
        "{%0,%1,%2,%3}, {%4,%5,%6,%7}, {%8,%9}, {%0,%1,%2,%3};"
        : "+f"(d[0]), "+f"(d[1]), "+f"(d[2]), "+f"(d[3])
        : "r"(a[0]), "r"(a[1]), "r"(a[2]), "r"(a[3]), "r"(b0), "r"(b1));
}

// ---------------- kernel 1: GroupNorm statistics + fused tf32 rounding of x ----------------
__global__ __launch_bounds__(1024) void gn_stats_kernel(const float* __restrict__ x) {
    int bg = blockIdx.x;
    const float4* p = reinterpret_cast<const float4*>(x) + (size_t)bg * (CPGc * HWc / 4);
    float4* dst = reinterpret_cast<float4*>(g_xr) + (size_t)bg * (CPGc * HWc / 4);
    float s = 0.f, ss = 0.f;
    const int n4 = CPGc * HWc / 4;
    for (int i = threadIdx.x; i < n4; i += blockDim.x) {
        float4 v = p[i];
        s  += (v.x + v.y) + (v.z + v.w);
        ss += (v.x * v.x + v.y * v.y) + (v.z * v.z + v.w * v.w);
        float4 r;
        r.x = rna_tf32(v.x); r.y = rna_tf32(v.y);
        r.z = rna_tf32(v.z); r.w = rna_tf32(v.w);
        dst[i] = r;
    }
    const unsigned FULL = 0xffffffffu;
    #pragma unroll
    for (int o = 16; o; o >>= 1) { s += __shfl_down_sync(FULL, s, o); ss += __shfl_down_sync(FULL, ss, o); }
    __shared__ float w1[32], w2[32];
    int lane = threadIdx.x & 31, wid = threadIdx.x >> 5;
    if (lane == 0) { w1[wid] = s; w2[wid] = ss; }
    __syncthreads();
    if (wid == 0) {
        int nw = blockDim.x >> 5;
        s  = (lane < nw) ? w1[lane] : 0.f;
        ss = (lane < nw) ? w2[lane] : 0.f;
        #pragma unroll
        for (int o = 16; o; o >>= 1) { s += __shfl_down_sync(FULL, s, o); ss += __shfl_down_sync(FULL, ss, o); }
        if (lane == 0) {
            const float invN = 1.f / (float)(CPGc * HWc);
            float mu  = s * invN;
            float var = ss * invN - mu * mu;
            g_mean[bg] = mu;
            g_rstd[bg] = rsqrtf(var + EPSc);
        }
    }
}

// ---------------- kernel 2: fold GN into qkv weights (tf32-rounded) ----------------
__global__ __launch_bounds__(256) void effw_kernel(
    const float* __restrict__ qw, const float* __restrict__ kw, const float* __restrict__ vw,
    const float* __restrict__ qb, const float* __restrict__ kb, const float* __restrict__ vb,
    const float* __restrict__ gnw, const float* __restrict__ gnb)
{
    int bo = blockIdx.x;
    int b = bo / 768, o = bo % 768;
    int t = o >> 8, oc = o & 255;
    const float* Wm   = (t == 0) ? qw : ((t == 1) ? kw : vw);
    const float* bias = (t == 0) ? qb : ((t == 1) ? kb : vb);
    int c = threadIdx.x;
    float w  = Wm[oc * 256 + c];
    int g    = c >> 3;
    float rs = g_rstd[b * Gc + g];
    float mu = g_mean[b * Gc + g];
    float sC = rs * gnw[c];
    float tC = gnb[c] - mu * sC;
    g_effw[(size_t)bo * 256 + c] = rna_tf32(w * sC);

    float v = w * tC;
    const unsigned FULL = 0xffffffffu;
    #pragma unroll
    for (int off = 16; off; off >>= 1) v += __shfl_down_sync(FULL, v, off);
    __shared__ float ws[8];
    int lane = c & 31, wid = c >> 5;
    if (lane == 0) ws[wid] = v;
    __syncthreads();
    if (c == 0) {
        float sum = 0.f;
        #pragma unroll
        for (int i = 0; i < 8; i++) sum += ws[i];
        g_effb[bo] = sum + bias[oc];
    }
}

__global__ __launch_bounds__(256) void round_ow_kernel(const float* __restrict__ ow) {
    int j = blockIdx.x * blockDim.x + threadIdx.x; // 16384 float4s
    float4 v = ((const float4*)ow)[j];
    v.x = rna_tf32(v.x); v.y = rna_tf32(v.y);
    v.z = rna_tf32(v.z); v.w = rna_tf32(v.w);
    ((float4*)g_owr)[j] = v;
}

// ---------------- kernels 3 & 5: tf32 mma.sync GEMM ----------------
// C[n][m] = sum_k A[k][m] * W[n][k]  (A m-contiguous), CTA tile 128m x 256n, BK=16.
// 16 warps: warp_m = wid&3 (4), warp_n = wid>>2 (4); warp tile 32x64.
// smem floats: A[3][16][136] at 0 (2176/stage), B[3][256][20] at 6528 (5120/stage).
#define SM_TOTAL_B 87552
#define NKI 16

template <bool OCONV>
__global__ void __launch_bounds__(512)
mma_gemm_kernel(const float* __restrict__ biasin, const float* __restrict__ resid,
                float* __restrict__ outp)
{
    extern __shared__ float sm[];
    const uint32_t sbase = smem_u32(sm);
    const int tid = threadIdx.x, lane = tid & 31, wid = tid >> 5;
    const int warp_m = wid & 3, warp_n = wid >> 2;
    const int ny = blockIdx.x;
    const size_t mbase = (size_t)blockIdx.y * 128;
    const int b = blockIdx.z;

    const float* Ag = (OCONV ? g_att : g_xr) + (size_t)b * Cc * HWc + mbase;
    const float* Wg = OCONV ? g_owr : (g_effw + ((size_t)b * 768 + ny * 256) * 256);

    float acc[2][8][4];
    #pragma unroll
    for (int i = 0; i < 2; i++)
        #pragma unroll
        for (int j = 0; j < 8; j++)
            #pragma unroll
            for (int l = 0; l < 4; l++) acc[i][j][l] = 0.f;

    auto issue = [&](int kt, int s) {
        const float* Asrc = Ag + (size_t)kt * 16 * HWc;
        uint32_t Ad = sbase + (uint32_t)(s * 2176) * 4u;
        {
            int k = tid >> 5, m4 = (tid & 31) << 2;
            cpasync16(Ad + (uint32_t)(k * 136 + m4) * 4u, Asrc + (size_t)k * HWc + m4);
        }
        const float* Bsrc = Wg + kt * 16;
        uint32_t Bd = sbase + (uint32_t)(6528 + s * 5120) * 4u;
        #pragma unroll
        for (int it = 0; it < 2; it++) {
            int lin = it * 512 + tid;
            int n = lin >> 2, k4 = (lin & 3) << 2;
            cpasync16(Bd + (uint32_t)(n * 20 + k4) * 4u, Bsrc + (size_t)n * 256 + k4);
        }
        asm volatile("cp.async.commit_group;" ::: "memory");
    };

    issue(0, 0);
    issue(1, 1);

    const int r = lane >> 2, c = lane & 3;
    #pragma unroll 1
    for (int kt = 0; kt < NKI; kt++) {
        const int cur = kt % 3;
        if (kt + 2 < NKI) issue(kt + 2, (kt + 2) % 3);
        if (kt < NKI - 2)      asm volatile("cp.async.wait_group 2;" ::: "memory");
        else if (kt == NKI - 2) asm volatile("cp.async.wait_group 1;" ::: "memory");
        else                   asm volatile("cp.async.wait_group 0;" ::: "memory");
        __syncthreads();

        const float* As = sm + cur * 2176;
        const float* Bs = sm + 6528 + cur * 5120;
        #pragma unroll
        for (int ks = 0; ks < 2; ks++) {
            const int kb = ks * 8;
            uint32_t af[2][4];
            #pragma unroll
            for (int mt = 0; mt < 2; mt++) {
                int m = warp_m * 32 + mt * 16 + r;
                af[mt][0] = __float_as_uint(As[(kb + c) * 136 + m]);
                af[mt][1] = __float_as_uint(As[(kb + c) * 136 + m + 8]);
                af[mt][2] = __float_as_uint(As[(kb + c + 4) * 136 + m]);
                af[mt][3] = __float_as_uint(As[(kb + c + 4) * 136 + m + 8]);
            }
            #pragma unroll
            for (int nt = 0; nt < 8; nt++) {
                int n = warp_n * 64 + nt * 8 + r;
                uint32_t b0 = __float_as_uint(Bs[n * 20 + kb + c]);
                uint32_t b1 = __float_as_uint(Bs[n * 20 + kb + c + 4]);
                #pragma unroll
                for (int mt = 0; mt < 2; mt++) mma1688(acc[mt][nt], af[mt], b0, b1);
            }
        }
        __syncthreads();
    }

    // ---------------- epilogue ----------------
    const float* bptr = OCONV ? biasin : (g_effb + b * 768 + ny * 256);
    #pragma unroll
    for (int nt = 0; nt < 8; nt++) {
        int nloc = warp_n * 64 + nt * 8 + 2 * (lane & 3);
        float b0v = bptr[nloc], b1v = bptr[nloc + 1];
        #pragma unroll
        for (int mt = 0; mt < 2; mt++) {
            size_t mg = mbase + warp_m * 32 + mt * 16 + (lane >> 2);
            if (OCONV) {
                size_t o0 = ((size_t)b * Cc + nloc) * HWc + mg;
                size_t o1 = o0 + HWc;
                outp[o0]     = (acc[mt][nt][0] + b0v + resid[o0]) * RSQRT2c;
                outp[o1]     = (acc[mt][nt][1] + b1v + resid[o1]) * RSQRT2c;
                outp[o0 + 8] = (acc[mt][nt][2] + b0v + resid[o0 + 8]) * RSQRT2c;
                outp[o1 + 8] = (acc[mt][nt][3] + b1v + resid[o1 + 8]) * RSQRT2c;
            } else {
                size_t o0 = ((size_t)(ny * Bc + b) * Cc + nloc) * HWc + mg;
                size_t o1 = o0 + HWc;
                g_qkv[o0]     = acc[mt][nt][0] + b0v;
                g_qkv[o1]     = acc[mt][nt][1] + b1v;
                g_qkv[o0 + 8] = acc[mt][nt][2] + b0v;
                g_qkv[o1 + 8] = acc[mt][nt][3] + b1v;
            }
        }
    }
}

// ---------------- kernel 4: windowed attention via tf32 mma ----------------
// Block = 128 threads (4 warps) per (window, head, batch). Warp w computes rows
// [16w, 16w+16) of the 64x64 S tile and the 16x32 O tile.
// K columns are staged permuted (per 8-group: token u -> col 2u (u<4), 2u-7 (u>=4))
// so the S-gemm C fragment IS the PV-gemm A fragment: a = {c0, c2, c1, c3}.
#define QK_STR 72
#define V_STR  40
__global__ __launch_bounds__(128) void attn_mma_kernel() {
    const int win = blockIdx.x, head = blockIdx.y, b = blockIdx.z;
    const int hpi = win >> 5, wpi = win & 31;

    __shared__ float qs[HDc][QK_STR];  // [hd][tok]
    __shared__ float ks[HDc][QK_STR];  // [hd][permuted tok]
    __shared__ float vs[64][V_STR];    // [tok][hd]

    const int tid = threadIdx.x, lane = tid & 31, wid = tid >> 5;
    const size_t TSTR = (size_t)Bc * Cc * HWc;
    const size_t base = ((size_t)b * Cc + head * HDc) * HWc
                      + (size_t)(hpi * Pc) * Wc + wpi * Pc;
    const float* qg = g_qkv + base;
    const float* kg = g_qkv + TSTR + base;
    const float* vg = g_qkv + 2 * TSTR + base;

    #pragma unroll
    for (int it = 0; it < 16; it++) {
        int i = it * 128 + tid;        // 0..2047
        int hd = i >> 6, tok = i & 63;
        size_t off = (size_t)hd * HWc + (size_t)(tok >> 3) * Wc + (tok & 7);
        int u = tok & 7;
        int np = (tok & ~7) | ((u < 4) ? (2 * u) : (2 * u - 7));
        qs[hd][tok] = rna_tf32(qg[off]);
        ks[hd][np]  = rna_tf32(kg[off]);
        vs[tok][hd] = rna_tf32(vg[off]);
    }
    __syncthreads();

    const int r4 = lane >> 2, cq = lane & 3;
    const int row = wid * 16 + r4;

    // ---- S = Q K^T  (16x64 per warp) ----
    float sacc[8][4];
    #pragma unroll
    for (int nt = 0; nt < 8; nt++)
        #pragma unroll
        for (int j = 0; j < 4; j++) sacc[nt][j] = 0.f;

    #pragma unroll
    for (int kt = 0; kt < 4; kt++) {
        uint32_t a[4];
        a[0] = __float_as_uint(qs[kt * 8 + cq][row]);
        a[1] = __float_as_uint(qs[kt * 8 + cq][row + 8]);
        a[2] = __float_as_uint(qs[kt * 8 + cq + 4][row]);
        a[3] = __float_as_uint(qs[kt * 8 + cq + 4][row + 8]);
        #pragma unroll
        for (int nt = 0; nt < 8; nt++) {
            uint32_t b0 = __float_as_uint(ks[kt * 8 + cq][nt * 8 + r4]);
            uint32_t b1 = __float_as_uint(ks[kt * 8 + cq + 4][nt * 8 + r4]);
            mma1688(sacc[nt], a, b0, b1);
        }
    }

    // ---- softmax over the 64 columns (rows r and r+8 per thread) ----
    const unsigned FULL = 0xffffffffu;
    float mx0 = -3.0e38f, mx1 = -3.0e38f;
    #pragma unroll
    for (int nt = 0; nt < 8; nt++) {
        mx0 = fmaxf(mx0, fmaxf(sacc[nt][0], sacc[nt][1]));
        mx1 = fmaxf(mx1, fmaxf(sacc[nt][2], sacc[nt][3]));
    }
    mx0 = fmaxf(mx0, __shfl_xor_sync(FULL, mx0, 1));
    mx0 = fmaxf(mx0, __shfl_xor_sync(FULL, mx0, 2));
    mx1 = fmaxf(mx1, __shfl_xor_sync(FULL, mx1, 1));
    mx1 = fmaxf(mx1, __shfl_xor_sync(FULL, mx1, 2));

    float sum0 = 0.f, sum1 = 0.f;
    #pragma unroll
    for (int nt = 0; nt < 8; nt++) {
        float e0 = rna_tf32(__expf((sacc[nt][0] - mx0) * ATTN_SCALE));
        float e1 = rna_tf32(__expf((sacc[nt][1] - mx0) * ATTN_SCALE));
        float e2 = rna_tf32(__expf((sacc[nt][2] - mx1) * ATTN_SCALE));
        float e3 = rna_tf32(__expf((sacc[nt][3] - mx1) * ATTN_SCALE));
        sacc[nt][0] = e0; sacc[nt][1] = e1; sacc[nt][2] = e2; sacc[nt][3] = e3;
        sum0 += e0 + e1; sum1 += e2 + e3;
    }
    sum0 += __shfl_xor_sync(FULL, sum0, 1);
    sum0 += __shfl_xor_sync(FULL, sum0, 2);
    sum1 += __shfl_xor_sync(FULL, sum1, 1);
    sum1 += __shfl_xor_sync(FULL, sum1, 2);
    const float inv0 = 1.f / sum0, inv1 = 1.f / sum1;

    // ---- O = P V  (16x32 per warp); P fragment = permuted S registers ----
    float oacc[4][4];
    #pragma unroll
    for (int nt = 0; nt < 4; nt++)
        #pragma unroll
        for (int j = 0; j < 4; j++) oacc[nt][j] = 0.f;

    #pragma unroll
    for (int kt = 0; kt < 8; kt++) {
        uint32_t a[4];
        a[0] = __float_as_uint(sacc[kt][0]);
        a[1] = __float_as_uint(sacc[kt][2]);
        a[2] = __float_as_uint(sacc[kt][1]);
        a[3] = __float_as_uint(sacc[kt][3]);
        #pragma unroll
        for (int nt = 0; nt < 4; nt++) {
            uint32_t b0 = __float_as_uint(vs[kt * 8 + cq][nt * 8 + r4]);
            uint32_t b1 = __float_as_uint(vs[kt * 8 + cq + 4][nt * 8 + r4]);
            mma1688(oacc[nt], a, b0, b1);
        }
    }

    // ---- write O (rows = tokens row, row+8; cols = hd) ----
    float* og = g_att + base;
    const int T0 = row, T1 = row + 8;
    const size_t sp0 = (size_t)(T0 >> 3) * Wc + (T0 & 7);
    const size_t sp1 = (size_t)(T1 >> 3) * Wc + (T1 & 7);
    #pragma unroll
    for (int nt = 0; nt < 4; nt++) {
        int hd0 = nt * 8 + 2 * cq;
        size_t c0 = (size_t)hd0 * HWc, c1 = c0 + HWc;
        og[c0 + sp0] = rna_tf32(oacc[nt][0] * inv0);
        og[c1 + sp0] = rna_tf32(oacc[nt][1] * inv0);
        og[c0 + sp1] = rna_tf32(oacc[nt][2] * inv1);
        og[c1 + sp1] = rna_tf32(oacc[nt][3] * inv1);
    }
}

// ---------------- launch ----------------
extern "C" void kernel_launch(void* const* d_in, const int* in_sizes, int n_in,
                              void* d_out, int out_size) {
    const float* x    = (const float*)d_in[0];
    const float* gn_w = (const float*)d_in[1];
    const float* gn_b = (const float*)d_in[2];
    const float* q_w  = (const float*)d_in[3];
    const float* q_b  = (const float*)d_in[4];
    const float* k_w  = (const float*)d_in[5];
    const float* k_b  = (const float*)d_in[6];
    const float* v_w  = (const float*)d_in[7];
    const float* v_b  = (const float*)d_in[8];
    const float* o_w  = (const float*)d_in[9];
    const float* o_b  = (const float*)d_in[10];
    float* out = (float*)d_out;

    cudaFuncSetAttribute(mma_gemm_kernel<false>,
                         cudaFuncAttributeMaxDynamicSharedMemorySize, SM_TOTAL_B);
    cudaFuncSetAttribute(mma_gemm_kernel<true>,
                         cudaFuncAttributeMaxDynamicSharedMemorySize, SM_TOTAL_B);

    gn_stats_kernel<<<Bc * Gc, 1024>>>(x);
    effw_kernel<<<Bc * 768, 256>>>(q_w, k_w, v_w, q_b, k_b, v_b, gn_w, gn_b);
    round_ow_kernel<<<64, 256>>>(o_w);

    dim3 gq(3, HWc / 128, Bc);
    mma_gemm_kernel<false><<<gq, 512, SM_TOTAL_B>>>(nullptr, nullptr, nullptr);

    dim3 ga(NWIN, NHc, Bc);
    attn_mma_kernel<<<ga, 128>>>();

    dim3 go(1, HWc / 128, Bc);
    mma_gemm_kernel<true><<<go, 512, SM_TOTAL_B>>>(o_b, x, out);
}

// round 8
// speedup vs baseline: 2.2415x; 1.0412x over previous
#include <cuda_runtime.h>
#include <cstdint>

// ---------------- problem constants ----------------
#define Bc   4
#define Cc   256
#define Hc   256
#define Wc   256
#define HWc  65536
#define NHc  8
#define HDc  32
#define Pc   8
#define Gc   32
#define CPGc 8
#define NWIN 1024
#define EPSc 1e-6f
#define ATTN_SCALE 0.17677669529663689f
#define RSQRT2c 0.70710678118654757f

typedef unsigned long long ull;

// ---------------- device scratch (no cudaMalloc allowed) ----------------
__device__ float g_mean[Bc * Gc];
__device__ float g_rstd[Bc * Gc];
__device__ float g_effw[(size_t)Bc * 768 * 256];   // GN-folded qkv weights (tf32-rounded)
__device__ float g_effb[Bc * 768];                 // folded bias (fp32)
__device__ float g_owr[256 * 256];                 // o_w tf32-rounded
__device__ float g_qkv[(size_t)3 * Bc * Cc * HWc]; // [t][b][c][h][w]  (805 MB)
__device__ float g_att[(size_t)Bc * Cc * HWc];     // attention out (256 MB)

// ---------------- helpers ----------------
__device__ __forceinline__ float rna_tf32(float x) {
    uint32_t r;
    asm("cvt.rna.tf32.f32 %0, %1;" : "=r"(r) : "f"(x));
    return __uint_as_float(r);
}
__device__ __forceinline__ uint32_t smem_u32(const void* p) {
    uint32_t a;
    asm("{ .reg .u64 t; cvta.to.shared.u64 t, %1; cvt.u32.u64 %0, t; }" : "=r"(a) : "l"(p));
    return a;
}
__device__ __forceinline__ void cpasync16(uint32_t dst, const void* src) {
    asm volatile("cp.async.cg.shared.global [%0], [%1], 16;" :: "r"(dst), "l"(src) : "memory");
}
__device__ __forceinline__ void mma1688(float* d, const uint32_t* a, uint32_t b0, uint32_t b1) {
    asm volatile(
        "mma.sync.aligned.m16n8k8.row.col.f32.tf32.tf32.f32 "
        "{%0,%1,%2,%3}, {%4,%5,%6,%7}, {%8,%9}, {%0,%1,%2,%3};"
        : "+f"(d[0]), "+f"(d[1]), "+f"(d[2]), "+f"(d[3])
        : "r"(a[0]), "r"(a[1]), "r"(a[2]), "r"(a[3]), "r"(b0), "r"(b1));
}
__device__ __forceinline__ void ldmx4(uint32_t* r, uint32_t addr) {
    asm volatile("ldmatrix.sync.aligned.m8n8.x4.shared.b16 {%0,%1,%2,%3}, [%4];"
        : "=r"(r[0]), "=r"(r[1]), "=r"(r[2]), "=r"(r[3]) : "r"(addr));
}

// ---------------- kernel 1: GroupNorm statistics ----------------
__global__ __launch_bounds__(1024) void gn_stats_kernel(const float* __restrict__ x) {
    int bg = blockIdx.x;
    const float4* p = reinterpret_cast<const float4*>(x) + (size_t)bg * (CPGc * HWc / 4);
    float s = 0.f, ss = 0.f;
    const int n4 = CPGc * HWc / 4;
    for (int i = threadIdx.x; i < n4; i += blockDim.x) {
        float4 v = p[i];
        s  += (v.x + v.y) + (v.z + v.w);
        ss += (v.x * v.x + v.y * v.y) + (v.z * v.z + v.w * v.w);
    }
    const unsigned FULL = 0xffffffffu;
    #pragma unroll
    for (int o = 16; o; o >>= 1) { s += __shfl_down_sync(FULL, s, o); ss += __shfl_down_sync(FULL, ss, o); }
    __shared__ float w1[32], w2[32];
    int lane = threadIdx.x & 31, wid = threadIdx.x >> 5;
    if (lane == 0) { w1[wid] = s; w2[wid] = ss; }
    __syncthreads();
    if (wid == 0) {
        int nw = blockDim.x >> 5;
        s  = (lane < nw) ? w1[lane] : 0.f;
        ss = (lane < nw) ? w2[lane] : 0.f;
        #pragma unroll
        for (int o = 16; o; o >>= 1) { s += __shfl_down_sync(FULL, s, o); ss += __shfl_down_sync(FULL, ss, o); }
        if (lane == 0) {
            const float invN = 1.f / (float)(CPGc * HWc);
            float mu  = s * invN;
            float var = ss * invN - mu * mu;
            g_mean[bg] = mu;
            g_rstd[bg] = rsqrtf(var + EPSc);
        }
    }
}

// ---------------- kernel 2: fold GN into qkv weights (tf32-rounded) ----------------
__global__ __launch_bounds__(256) void effw_kernel(
    const float* __restrict__ qw, const float* __restrict__ kw, const float* __restrict__ vw,
    const float* __restrict__ qb, const float* __restrict__ kb, const float* __restrict__ vb,
    const float* __restrict__ gnw, const float* __restrict__ gnb)
{
    int bo = blockIdx.x;
    int b = bo / 768, o = bo % 768;
    int t = o >> 8, oc = o & 255;
    const float* Wm   = (t == 0) ? qw : ((t == 1) ? kw : vw);
    const float* bias = (t == 0) ? qb : ((t == 1) ? kb : vb);
    int c = threadIdx.x;
    float w  = Wm[oc * 256 + c];
    int g    = c >> 3;
    float rs = g_rstd[b * Gc + g];
    float mu = g_mean[b * Gc + g];
    float sC = rs * gnw[c];
    float tC = gnb[c] - mu * sC;
    g_effw[(size_t)bo * 256 + c] = rna_tf32(w * sC);

    float v = w * tC;
    const unsigned FULL = 0xffffffffu;
    #pragma unroll
    for (int off = 16; off; off >>= 1) v += __shfl_down_sync(FULL, v, off);
    __shared__ float ws[8];
    int lane = c & 31, wid = c >> 5;
    if (lane == 0) ws[wid] = v;
    __syncthreads();
    if (c == 0) {
        float sum = 0.f;
        #pragma unroll
        for (int i = 0; i < 8; i++) sum += ws[i];
        g_effb[bo] = sum + bias[oc];
    }
}

__global__ __launch_bounds__(256) void round_ow_kernel(const float* __restrict__ ow) {
    int j = blockIdx.x * blockDim.x + threadIdx.x; // 16384 float4s
    float4 v = ((const float4*)ow)[j];
    v.x = rna_tf32(v.x); v.y = rna_tf32(v.y);
    v.z = rna_tf32(v.z); v.w = rna_tf32(v.w);
    ((float4*)g_owr)[j] = v;
}

// ---------------- kernels 3 & 5: tf32 mma.sync GEMM ----------------
// C[n][m] = sum_k A[k][m] * W[n][k]  (A m-contiguous), CTA tile 128m x 256n, BK=16.
// 16 warps: warp_m = wid&3 (4), warp_n = wid>>2 (4); warp tile 32x64.
// smem floats: A[4][16][136] at 0 (2176/stage), B[4][256][20] at 8704 (5120/stage).
// 4-stage cp.async pipeline, ONE __syncthreads per iter, B frags via ldmatrix.
#define SM_TOTAL_B 116736
#define NKI 16

template <bool OCONV>
__global__ void __launch_bounds__(512)
mma_gemm_kernel(const float* __restrict__ Ain, const float* __restrict__ biasin,
                const float* __restrict__ resid, float* __restrict__ outp)
{
    extern __shared__ float sm[];
    const uint32_t sbase = smem_u32(sm);
    const int tid = threadIdx.x, lane = tid & 31, wid = tid >> 5;
    const int warp_m = wid & 3, warp_n = wid >> 2;
    const int ny = blockIdx.x;
    const size_t mbase = (size_t)blockIdx.y * 128;
    const int b = blockIdx.z;

    const float* Ag = (OCONV ? g_att : Ain) + (size_t)b * Cc * HWc + mbase;
    const float* Wg = OCONV ? g_owr : (g_effw + ((size_t)b * 768 + ny * 256) * 256);

    float acc[2][8][4];
    #pragma unroll
    for (int i = 0; i < 2; i++)
        #pragma unroll
        for (int j = 0; j < 8; j++)
            #pragma unroll
            for (int l = 0; l < 4; l++) acc[i][j][l] = 0.f;

    auto issue = [&](int kt, int s) {
        const float* Asrc = Ag + (size_t)kt * 16 * HWc;
        uint32_t Ad = sbase + (uint32_t)(s * 2176) * 4u;
        {
            int k = tid >> 5, m4 = (tid & 31) << 2;
            cpasync16(Ad + (uint32_t)(k * 136 + m4) * 4u, Asrc + (size_t)k * HWc + m4);
        }
        const float* Bsrc = Wg + kt * 16;
        uint32_t Bd = sbase + (uint32_t)(8704 + s * 5120) * 4u;
        #pragma unroll
        for (int it = 0; it < 2; it++) {
            int lin = it * 512 + tid;
            int n = lin >> 2, k4 = (lin & 3) << 2;
            cpasync16(Bd + (uint32_t)(n * 20 + k4) * 4u, Bsrc + (size_t)n * 256 + k4);
        }
        asm volatile("cp.async.commit_group;" ::: "memory");
    };

    issue(0, 0);
    issue(1, 1);
    issue(2, 2);

    const int r = lane >> 2, c = lane & 3;
    // per-thread ldmatrix row offset (words): row-within-16 block + k-half select
    const uint32_t boff = ((uint32_t)((lane >> 3) & 1) * 8 + (lane & 7)) * 20 + ((lane >> 4) << 2);

    #pragma unroll 1
    for (int kt = 0; kt < NKI; kt++) {
        const int cur = kt & 3;
        if (kt < NKI - 2)       asm volatile("cp.async.wait_group 2;" ::: "memory");
        else if (kt == NKI - 2) asm volatile("cp.async.wait_group 1;" ::: "memory");
        else                    asm volatile("cp.async.wait_group 0;" ::: "memory");
        __syncthreads();
        if (kt + 3 < NKI) issue(kt + 3, (kt + 3) & 3);

        const float* As = sm + cur * 2176;
        const uint32_t Bsu = sbase + (uint32_t)(8704 + cur * 5120) * 4u
                           + (uint32_t)(warp_n * 64 * 20) * 4u;
        #pragma unroll
        for (int ks = 0; ks < 2; ks++) {
            const int kb = ks * 8;
            uint32_t af[2][4];
            #pragma unroll
            for (int mt = 0; mt < 2; mt++) {
                int m = warp_m * 32 + mt * 16 + r;
                af[mt][0] = __float_as_uint(As[(kb + c) * 136 + m]);
                af[mt][1] = __float_as_uint(As[(kb + c) * 136 + m + 8]);
                af[mt][2] = __float_as_uint(As[(kb + c + 4) * 136 + m]);
                af[mt][3] = __float_as_uint(As[(kb + c + 4) * 136 + m + 8]);
            }
            #pragma unroll
            for (int g = 0; g < 4; g++) {
                uint32_t bf[4];
                ldmx4(bf, Bsu + (uint32_t)(g * 320 + kb + boff) * 4u);
                mma1688(acc[0][2 * g],     af[0], bf[0], bf[2]);
                mma1688(acc[1][2 * g],     af[1], bf[0], bf[2]);
                mma1688(acc[0][2 * g + 1], af[0], bf[1], bf[3]);
                mma1688(acc[1][2 * g + 1], af[1], bf[1], bf[3]);
            }
        }
    }

    // ---------------- epilogue ----------------
    const float* bptr = OCONV ? biasin : (g_effb + b * 768 + ny * 256);
    #pragma unroll
    for (int nt = 0; nt < 8; nt++) {
        int nloc = warp_n * 64 + nt * 8 + 2 * (lane & 3);
        float b0v = bptr[nloc], b1v = bptr[nloc + 1];
        #pragma unroll
        for (int mt = 0; mt < 2; mt++) {
            size_t mg = mbase + warp_m * 32 + mt * 16 + (lane >> 2);
            if (OCONV) {
                size_t o0 = ((size_t)b * Cc + nloc) * HWc + mg;
                size_t o1 = o0 + HWc;
                outp[o0]     = (acc[mt][nt][0] + b0v + resid[o0]) * RSQRT2c;
                outp[o1]     = (acc[mt][nt][1] + b1v + resid[o1]) * RSQRT2c;
                outp[o0 + 8] = (acc[mt][nt][2] + b0v + resid[o0 + 8]) * RSQRT2c;
                outp[o1 + 8] = (acc[mt][nt][3] + b1v + resid[o1 + 8]) * RSQRT2c;
            } else {
                size_t o0 = ((size_t)(ny * Bc + b) * Cc + nloc) * HWc + mg;
                size_t o1 = o0 + HWc;
                g_qkv[o0]     = acc[mt][nt][0] + b0v;
                g_qkv[o1]     = acc[mt][nt][1] + b1v;
                g_qkv[o0 + 8] = acc[mt][nt][2] + b0v;
                g_qkv[o1 + 8] = acc[mt][nt][3] + b1v;
            }
        }
    }
}

// ---------------- kernel 4: windowed attention via tf32 mma ----------------
// Block = 128 threads (4 warps) per (window, head, batch). Warp w computes rows
// [16w, 16w+16) of the 64x64 S tile and the 16x32 O tile.
// K columns are staged permuted (per 8-group: token u -> col 2u (u<4), 2u-7 (u>=4))
// so the S-gemm C fragment IS the PV-gemm A fragment: a = {c0, c2, c1, c3}.
#define QK_STR 72
#define V_STR  40
__global__ __launch_bounds__(128) void attn_mma_kernel() {
    const int win = blockIdx.x, head = blockIdx.y, b = blockIdx.z;
    const int hpi = win >> 5, wpi = win & 31;

    __shared__ float qs[HDc][QK_STR];  // [hd][tok]
    __shared__ float ks[HDc][QK_STR];  // [hd][permuted tok]
    __shared__ float vs[64][V_STR];    // [tok][hd]

    const int tid = threadIdx.x, lane = tid & 31, wid = tid >> 5;
    const size_t TSTR = (size_t)Bc * Cc * HWc;
    const size_t base = ((size_t)b * Cc + head * HDc) * HWc
                      + (size_t)(hpi * Pc) * Wc + wpi * Pc;
    const float* qg = g_qkv + base;
    const float* kg = g_qkv + TSTR + base;
    const float* vg = g_qkv + 2 * TSTR + base;

    #pragma unroll
    for (int it = 0; it < 16; it++) {
        int i = it * 128 + tid;        // 0..2047
        int hd = i >> 6, tok = i & 63;
        size_t off = (size_t)hd * HWc + (size_t)(tok >> 3) * Wc + (tok & 7);
        int u = tok & 7;
        int np = (tok & ~7) | ((u < 4) ? (2 * u) : (2 * u - 7));
        qs[hd][tok] = rna_tf32(qg[off]);
        ks[hd][np]  = rna_tf32(kg[off]);
        vs[tok][hd] = rna_tf32(vg[off]);
    }
    __syncthreads();

    const int r4 = lane >> 2, cq = lane & 3;
    const int row = wid * 16 + r4;

    // ---- S = Q K^T  (16x64 per warp) ----
    float sacc[8][4];
    #pragma unroll
    for (int nt = 0; nt < 8; nt++)
        #pragma unroll
        for (int j = 0; j < 4; j++) sacc[nt][j] = 0.f;

    #pragma unroll
    for (int kt = 0; kt < 4; kt++) {
        uint32_t a[4];
        a[0] = __float_as_uint(qs[kt * 8 + cq][row]);
        a[1] = __float_as_uint(qs[kt * 8 + cq][row + 8]);
        a[2] = __float_as_uint(qs[kt * 8 + cq + 4][row]);
        a[3] = __float_as_uint(qs[kt * 8 + cq + 4][row + 8]);
        #pragma unroll
        for (int nt = 0; nt < 8; nt++) {
            uint32_t b0 = __float_as_uint(ks[kt * 8 + cq][nt * 8 + r4]);
            uint32_t b1 = __float_as_uint(ks[kt * 8 + cq + 4][nt * 8 + r4]);
            mma1688(sacc[nt], a, b0, b1);
        }
    }

    // ---- softmax over the 64 columns (rows r and r+8 per thread) ----
    const unsigned FULL = 0xffffffffu;
    float mx0 = -3.0e38f, mx1 = -3.0e38f;
    #pragma unroll
    for (int nt = 0; nt < 8; nt++) {
        mx0 = fmaxf(mx0, fmaxf(sacc[nt][0], sacc[nt][1]));
        mx1 = fmaxf(mx1, fmaxf(sacc[nt][2], sacc[nt][3]));
    }
    mx0 = fmaxf(mx0, __shfl_xor_sync(FULL, mx0, 1));
    mx0 = fmaxf(mx0, __shfl_xor_sync(FULL, mx0, 2));
    mx1 = fmaxf(mx1, __shfl_xor_sync(FULL, mx1, 1));
    mx1 = fmaxf(mx1, __shfl_xor_sync(FULL, mx1, 2));

    float sum0 = 0.f, sum1 = 0.f;
    #pragma unroll
    for (int nt = 0; nt < 8; nt++) {
        float e0 = rna_tf32(__expf((sacc[nt][0] - mx0) * ATTN_SCALE));
        float e1 = rna_tf32(__expf((sacc[nt][1] - mx0) * ATTN_SCALE));
        float e2 = rna_tf32(__expf((sacc[nt][2] - mx1) * ATTN_SCALE));
        float e3 = rna_tf32(__expf((sacc[nt][3] - mx1) * ATTN_SCALE));
        sacc[nt][0] = e0; sacc[nt][1] = e1; sacc[nt][2] = e2; sacc[nt][3] = e3;
        sum0 += e0 + e1; sum1 += e2 + e3;
    }
    sum0 += __shfl_xor_sync(FULL, sum0, 1);
    sum0 += __shfl_xor_sync(FULL, sum0, 2);
    sum1 += __shfl_xor_sync(FULL, sum1, 1);
    sum1 += __shfl_xor_sync(FULL, sum1, 2);
    const float inv0 = 1.f / sum0, inv1 = 1.f / sum1;

    // ---- O = P V  (16x32 per warp); P fragment = permuted S registers ----
    float oacc[4][4];
    #pragma unroll
    for (int nt = 0; nt < 4; nt++)
        #pragma unroll
        for (int j = 0; j < 4; j++) oacc[nt][j] = 0.f;

    #pragma unroll
    for (int kt = 0; kt < 8; kt++) {
        uint32_t a[4];
        a[0] = __float_as_uint(sacc[kt][0]);
        a[1] = __float_as_uint(sacc[kt][2]);
        a[2] = __float_as_uint(sacc[kt][1]);
        a[3] = __float_as_uint(sacc[kt][3]);
        #pragma unroll
        for (int nt = 0; nt < 4; nt++) {
            uint32_t b0 = __float_as_uint(vs[kt * 8 + cq][nt * 8 + r4]);
            uint32_t b1 = __float_as_uint(vs[kt * 8 + cq + 4][nt * 8 + r4]);
            mma1688(oacc[nt], a, b0, b1);
        }
    }

    // ---- write O (rows = tokens row, row+8; cols = hd) ----
    float* og = g_att + base;
    const int T0 = row, T1 = row + 8;
    const size_t sp0 = (size_t)(T0 >> 3) * Wc + (T0 & 7);
    const size_t sp1 = (size_t)(T1 >> 3) * Wc + (T1 & 7);
    #pragma unroll
    for (int nt = 0; nt < 4; nt++) {
        int hd0 = nt * 8 + 2 * cq;
        size_t c0 = (size_t)hd0 * HWc, c1 = c0 + HWc;
        og[c0 + sp0] = rna_tf32(oacc[nt][0] * inv0);
        og[c1 + sp0] = rna_tf32(oacc[nt][1] * inv0);
        og[c0 + sp1] = rna_tf32(oacc[nt][2] * inv1);
        og[c1 + sp1] = rna_tf32(oacc[nt][3] * inv1);
    }
}

// ---------------- launch ----------------
extern "C" void kernel_launch(void* const* d_in, const int* in_sizes, int n_in,
                              void* d_out, int out_size) {
    const float* x    = (const float*)d_in[0];
    const float* gn_w = (const float*)d_in[1];
    const float* gn_b = (const float*)d_in[2];
    const float* q_w  = (const float*)d_in[3];
    const float* q_b  = (const float*)d_in[4];
    const float* k_w  = (const float*)d_in[5];
    const float* k_b  = (const float*)d_in[6];
    const float* v_w  = (const float*)d_in[7];
    const float* v_b  = (const float*)d_in[8];
    const float* o_w  = (const float*)d_in[9];
    const float* o_b  = (const float*)d_in[10];
    float* out = (float*)d_out;

    cudaFuncSetAttribute(mma_gemm_kernel<false>,
                         cudaFuncAttributeMaxDynamicSharedMemorySize, SM_TOTAL_B);
    cudaFuncSetAttribute(mma_gemm_kernel<true>,
                         cudaFuncAttributeMaxDynamicSharedMemorySize, SM_TOTAL_B);

    gn_stats_kernel<<<Bc * Gc, 1024>>>(x);
    effw_kernel<<<Bc * 768, 256>>>(q_w, k_w, v_w, q_b, k_b, v_b, gn_w, gn_b);
    round_ow_kernel<<<64, 256>>>(o_w);

    dim3 gq(3, HWc / 128, Bc);
    mma_gemm_kernel<false><<<gq, 512, SM_TOTAL_B>>>(x, nullptr, nullptr, nullptr);

    dim3 ga(NWIN, NHc, Bc);
    attn_mma_kernel<<<ga, 128>>>();

    dim3 go(1, HWc / 128, Bc);
    mma_gemm_kernel<true><<<go, 512, SM_TOTAL_B>>>(nullptr, o_b, x, out);
}

// round 10
// speedup vs baseline: 2.2843x; 1.0191x over previous
#include <cuda_runtime.h>
#include <cstdint>

// ---------------- problem constants ----------------
#define Bc   4
#define Cc   256
#define Hc   256
#define Wc   256
#define HWc  65536
#define NHc  8
#define HDc  32
#define Pc   8
#define Gc   32
#define CPGc 8
#define NWIN 1024
#define EPSc 1e-6f
#define ATTN_SCALE 0.17677669529663689f
#define RSQRT2c 0.70710678118654757f

typedef unsigned long long ull;

// ---------------- device scratch (no cudaMalloc allowed) ----------------
__device__ float g_mean[Bc * Gc];
__device__ float g_rstd[Bc * Gc];
__device__ float g_effw[(size_t)Bc * 768 * 256];   // GN-folded qkv weights (tf32-rounded)
__device__ float g_effb[Bc * 768];                 // folded bias (fp32)
__device__ float g_owr[256 * 256];                 // o_w tf32-rounded
__device__ float g_qkv[(size_t)3 * Bc * Cc * HWc]; // [t][b][c][h][w]  (805 MB)
__device__ float g_att[(size_t)Bc * Cc * HWc];     // attention out (256 MB)

// ---------------- helpers ----------------
__device__ __forceinline__ float rna_tf32(float x) {
    uint32_t r;
    asm("cvt.rna.tf32.f32 %0, %1;" : "=r"(r) : "f"(x));
    return __uint_as_float(r);
}
__device__ __forceinline__ uint32_t smem_u32(const void* p) {
    uint32_t a;
    asm("{ .reg .u64 t; cvta.to.shared.u64 t, %1; cvt.u32.u64 %0, t; }" : "=r"(a) : "l"(p));
    return a;
}
__device__ __forceinline__ void cpasync16(uint32_t dst, const void* src) {
    asm volatile("cp.async.cg.shared.global [%0], [%1], 16;" :: "r"(dst), "l"(src) : "memory");
}
__device__ __forceinline__ void mma1688(float* d, const uint32_t* a, uint32_t b0, uint32_t b1) {
    asm volatile(
        "mma.sync.aligned.m16n8k8.row.col.f32.tf32.tf32.f32 "
        "{%0,%1,%2,%3}, {%4,%5,%6,%7}, {%8,%9}, {%0,%1,%2,%3};"
        : "+f"(d[0]), "+f"(d[1]), "+f"(d[2]), "+f"(d[3])
        : "r"(a[0]), "r"(a[1]), "r"(a[2]), "r"(a[3]), "r"(b0), "r"(b1));
}
__device__ __forceinline__ void ldmx4(uint32_t* r, uint32_t addr) {
    asm volatile("ldmatrix.sync.aligned.m8n8.x4.shared.b16 {%0,%1,%2,%3}, [%4];"
        : "=r"(r[0]), "=r"(r[1]), "=r"(r[2]), "=r"(r[3]) : "r"(addr));
}

// ---------------- kernel 1: GroupNorm statistics ----------------
__global__ __launch_bounds__(1024) void gn_stats_kernel(const float* __restrict__ x) {
    int bg = blockIdx.x;
    const float4* p = reinterpret_cast<const float4*>(x) + (size_t)bg * (CPGc * HWc / 4);
    float s = 0.f, ss = 0.f;
    const int n4 = CPGc * HWc / 4;
    for (int i = threadIdx.x; i < n4; i += blockDim.x) {
        float4 v = p[i];
        s  += (v.x + v.y) + (v.z + v.w);
        ss += (v.x * v.x + v.y * v.y) + (v.z * v.z + v.w * v.w);
    }
    const unsigned FULL = 0xffffffffu;
    #pragma unroll
    for (int o = 16; o; o >>= 1) { s += __shfl_down_sync(FULL, s, o); ss += __shfl_down_sync(FULL, ss, o); }
    __shared__ float w1[32], w2[32];
    int lane = threadIdx.x & 31, wid = threadIdx.x >> 5;
    if (lane == 0) { w1[wid] = s; w2[wid] = ss; }
    __syncthreads();
    if (wid == 0) {
        int nw = blockDim.x >> 5;
        s  = (lane < nw) ? w1[lane] : 0.f;
        ss = (lane < nw) ? w2[lane] : 0.f;
        #pragma unroll
        for (int o = 16; o; o >>= 1) { s += __shfl_down_sync(FULL, s, o); ss += __shfl_down_sync(FULL, ss, o); }
        if (lane == 0) {
            const float invN = 1.f / (float)(CPGc * HWc);
            float mu  = s * invN;
            float var = ss * invN - mu * mu;
            g_mean[bg] = mu;
            g_rstd[bg] = rsqrtf(var + EPSc);
        }
    }
}

// ---------------- kernel 2: fold GN into qkv weights (tf32-rounded) ----------------
__global__ __launch_bounds__(256) void effw_kernel(
    const float* __restrict__ qw, const float* __restrict__ kw, const float* __restrict__ vw,
    const float* __restrict__ qb, const float* __restrict__ kb, const float* __restrict__ vb,
    const float* __restrict__ gnw, const float* __restrict__ gnb)
{
    int bo = blockIdx.x;
    int b = bo / 768, o = bo % 768;
    int t = o >> 8, oc = o & 255;
    const float* Wm   = (t == 0) ? qw : ((t == 1) ? kw : vw);
    const float* bias = (t == 0) ? qb : ((t == 1) ? kb : vb);
    int c = threadIdx.x;
    float w  = Wm[oc * 256 + c];
    int g    = c >> 3;
    float rs = g_rstd[b * Gc + g];
    float mu = g_mean[b * Gc + g];
    float sC = rs * gnw[c];
    float tC = gnb[c] - mu * sC;
    g_effw[(size_t)bo * 256 + c] = rna_tf32(w * sC);

    float v = w * tC;
    const unsigned FULL = 0xffffffffu;
    #pragma unroll
    for (int off = 16; off; off >>= 1) v += __shfl_down_sync(FULL, v, off);
    __shared__ float ws[8];
    int lane = c & 31, wid = c >> 5;
    if (lane == 0) ws[wid] = v;
    __syncthreads();
    if (c == 0) {
        float sum = 0.f;
        #pragma unroll
        for (int i = 0; i < 8; i++) sum += ws[i];
        g_effb[bo] = sum + bias[oc];
    }
}

__global__ __launch_bounds__(256) void round_ow_kernel(const float* __restrict__ ow) {
    int j = blockIdx.x * blockDim.x + threadIdx.x; // 16384 float4s
    float4 v = ((const float4*)ow)[j];
    v.x = rna_tf32(v.x); v.y = rna_tf32(v.y);
    v.z = rna_tf32(v.z); v.w = rna_tf32(v.w);
    ((float4*)g_owr)[j] = v;
}

// ---------------- kernels 3 & 5: tf32 mma.sync GEMM v3 ----------------
// C[n][m] = sum_k A[k][m] * W[n][k]  (A m-contiguous). CTA tile 128m x 256n, BK=32.
// 8 warps: warp_m = wid&1 (2), warp_n = wid>>1 (4); warp tile 64x64.
// smem floats per stage: A[32][136] = 4352, B[256][36] = 9216 -> 13568 words.
// 3 stages: 40704 words = 162816 B. One __syncthreads per iter; B frags via ldmatrix.
#define ASTG 4352
#define BSTG 9216
#define STGW 13568
#define BOFFW (3 * ASTG)          // B region starts after 3 A stages? NO -- interleaved per-stage below
#define SM_TOTAL_B (3 * STGW * 4) // 162816 bytes
#define NKI 8

template <bool OCONV>
__global__ void __launch_bounds__(256)
mma_gemm_kernel(const float* __restrict__ Ain, const float* __restrict__ biasin,
                const float* __restrict__ resid, float* __restrict__ outp)
{
    extern __shared__ float sm[];
    const uint32_t sbase = smem_u32(sm);
    const int tid = threadIdx.x, lane = tid & 31, wid = tid >> 5;
    const int warp_m = wid & 1, warp_n = wid >> 1;
    const int ny = blockIdx.x;
    const size_t mbase = (size_t)blockIdx.y * 128;
    const int b = blockIdx.z;

    const float* Ag = (OCONV ? g_att : Ain) + (size_t)b * Cc * HWc + mbase;
    const float* Wg = OCONV ? g_owr : (g_effw + ((size_t)b * 768 + ny * 256) * 256);

    float acc[4][8][4];
    #pragma unroll
    for (int i = 0; i < 4; i++)
        #pragma unroll
        for (int j = 0; j < 8; j++)
            #pragma unroll
            for (int l = 0; l < 4; l++) acc[i][j][l] = 0.f;

    // stage s: A at s*STGW, B at s*STGW + ASTG (words)
    auto issue = [&](int kt, int s) {
        const float* Asrc = Ag + (size_t)kt * 32 * HWc;
        uint32_t Ad = sbase + (uint32_t)(s * STGW) * 4u;
        #pragma unroll
        for (int it = 0; it < 4; it++) {
            int lin = it * 256 + tid;          // 0..1023
            int k = lin >> 5, m4 = (lin & 31) << 2;
            cpasync16(Ad + (uint32_t)(k * 136 + m4) * 4u, Asrc + (size_t)k * HWc + m4);
        }
        const float* Bsrc = Wg + kt * 32;
        uint32_t Bd = sbase + (uint32_t)(s * STGW + ASTG) * 4u;
        #pragma unroll
        for (int it = 0; it < 8; it++) {
            int lin = it * 256 + tid;          // 0..2047
            int n = lin >> 3, k4 = (lin & 7) << 2;
            cpasync16(Bd + (uint32_t)(n * 36 + k4) * 4u, Bsrc + (size_t)n * 256 + k4);
        }
        asm volatile("cp.async.commit_group;" ::: "memory");
    };

    issue(0, 0);
    issue(1, 1);

    const int r = lane >> 2, c = lane & 3;
    // ldmatrix per-lane row offset (words), stride 36: row-within-16 + k-half select
    const uint32_t boff = ((uint32_t)((lane >> 3) & 1) * 8 + (lane & 7)) * 36 + ((lane >> 4) << 2);

    #pragma unroll 1
    for (int kt = 0; kt < NKI; kt++) {
        const int cur = kt % 3;
        if (kt == NKI - 1) asm volatile("cp.async.wait_group 0;" ::: "memory");
        else               asm volatile("cp.async.wait_group 1;" ::: "memory");
        __syncthreads();
        if (kt + 2 < NKI) issue(kt + 2, (kt + 2) % 3);

        const float* As = sm + cur * STGW;
        const uint32_t Bsu = sbase + (uint32_t)(cur * STGW + ASTG) * 4u
                           + (uint32_t)(warp_n * 64 * 36) * 4u;
        #pragma unroll
        for (int ks = 0; ks < 4; ks++) {
            const int kb = ks * 8;
            uint32_t af[4][4];
            #pragma unroll
            for (int mt = 0; mt < 4; mt++) {
                int m = warp_m * 64 + mt * 16 + r;
                af[mt][0] = __float_as_uint(As[(kb + c) * 136 + m]);
                af[mt][1] = __float_as_uint(As[(kb + c) * 136 + m + 8]);
                af[mt][2] = __float_as_uint(As[(kb + c + 4) * 136 + m]);
                af[mt][3] = __float_as_uint(As[(kb + c + 4) * 136 + m + 8]);
            }
            #pragma unroll
            for (int g = 0; g < 4; g++) {
                uint32_t bf[4];
                ldmx4(bf, Bsu + (uint32_t)(g * 16 * 36 + kb + boff) * 4u);
                #pragma unroll
                for (int mt = 0; mt < 4; mt++) {
                    mma1688(acc[mt][2 * g],     af[mt], bf[0], bf[2]);
                    mma1688(acc[mt][2 * g + 1], af[mt], bf[1], bf[3]);
                }
            }
        }
    }

    // ---------------- epilogue ----------------
    const float* bptr = OCONV ? biasin : (g_effb + b * 768 + ny * 256);
    #pragma unroll
    for (int nt = 0; nt < 8; nt++) {
        int nloc = warp_n * 64 + nt * 8 + 2 * (lane & 3);
        float b0v = bptr[nloc], b1v = bptr[nloc + 1];
        #pragma unroll
        for (int mt = 0; mt < 4; mt++) {
            size_t mg = mbase + warp_m * 64 + mt * 16 + (lane >> 2);
            if (OCONV) {
                size_t o0 = ((size_t)b * Cc + nloc) * HWc + mg;
                size_t o1 = o0 + HWc;
                outp[o0]     = (acc[mt][nt][0] + b0v + resid[o0]) * RSQRT2c;
                outp[o1]     = (acc[mt][nt][1] + b1v + resid[o1]) * RSQRT2c;
                outp[o0 + 8] = (acc[mt][nt][2] + b0v + resid[o0 + 8]) * RSQRT2c;
                outp[o1 + 8] = (acc[mt][nt][3] + b1v + resid[o1 + 8]) * RSQRT2c;
            } else {
                size_t o0 = ((size_t)(ny * Bc + b) * Cc + nloc) * HWc + mg;
                size_t o1 = o0 + HWc;
                g_qkv[o0]     = acc[mt][nt][0] + b0v;
                g_qkv[o1]     = acc[mt][nt][1] + b1v;
                g_qkv[o0 + 8] = acc[mt][nt][2] + b0v;
                g_qkv[o1 + 8] = acc[mt][nt][3] + b1v;
            }
        }
    }
}

// ---------------- kernel 4: windowed attention via tf32 mma ----------------
// Block = 128 threads (4 warps) per (window, head, batch). Warp w computes rows
// [16w, 16w+16) of the 64x64 S tile and the 16x32 O tile.
// K columns are staged permuted (per 8-group: token u -> col 2u (u<4), 2u-7 (u>=4))
// so the S-gemm C fragment IS the PV-gemm A fragment: a = {c0, c2, c1, c3}.
#define QK_STR 72
#define V_STR  40
__global__ __launch_bounds__(128) void attn_mma_kernel() {
    const int win = blockIdx.x, head = blockIdx.y, b = blockIdx.z;
    const int hpi = win >> 5, wpi = win & 31;

    __shared__ float qs[HDc][QK_STR];  // [hd][tok]
    __shared__ float ks[HDc][QK_STR];  // [hd][permuted tok]
    __shared__ float vs[64][V_STR];    // [tok][hd]

    const int tid = threadIdx.x, lane = tid & 31, wid = tid >> 5;
    const size_t TSTR = (size_t)Bc * Cc * HWc;
    const size_t base = ((size_t)b * Cc + head * HDc) * HWc
                      + (size_t)(hpi * Pc) * Wc + wpi * Pc;
    const float* qg = g_qkv + base;
    const float* kg = g_qkv + TSTR + base;
    const float* vg = g_qkv + 2 * TSTR + base;

    #pragma unroll
    for (int it = 0; it < 16; it++) {
        int i = it * 128 + tid;        // 0..2047
        int hd = i >> 6, tok = i & 63;
        size_t off = (size_t)hd * HWc + (size_t)(tok >> 3) * Wc + (tok & 7);
        int u = tok & 7;
        int np = (tok & ~7) | ((u < 4) ? (2 * u) : (2 * u - 7));
        qs[hd][tok] = rna_tf32(qg[off]);
        ks[hd][np]  = rna_tf32(kg[off]);
        vs[tok][hd] = rna_tf32(vg[off]);
    }
    __syncthreads();

    const int r4 = lane >> 2, cq = lane & 3;
    const int row = wid * 16 + r4;

    // ---- S = Q K^T  (16x64 per warp) ----
    float sacc[8][4];
    #pragma unroll
    for (int nt = 0; nt < 8; nt++)
        #pragma unroll
        for (int j = 0; j < 4; j++) sacc[nt][j] = 0.f;

    #pragma unroll
    for (int kt = 0; kt < 4; kt++) {
        uint32_t a[4];
        a[0] = __float_as_uint(qs[kt * 8 + cq][row]);
        a[1] = __float_as_uint(qs[kt * 8 + cq][row + 8]);
        a[2] = __float_as_uint(qs[kt * 8 + cq + 4][row]);
        a[3] = __float_as_uint(qs[kt * 8 + cq + 4][row + 8]);
        #pragma unroll
        for (int nt = 0; nt < 8; nt++) {
            uint32_t b0 = __float_as_uint(ks[kt * 8 + cq][nt * 8 + r4]);
            uint32_t b1 = __float_as_uint(ks[kt * 8 + cq + 4][nt * 8 + r4]);
            mma1688(sacc[nt], a, b0, b1);
        }
    }

    // ---- softmax over the 64 columns (rows r and r+8 per thread) ----
    const unsigned FULL = 0xffffffffu;
    float mx0 = -3.0e38f, mx1 = -3.0e38f;
    #pragma unroll
    for (int nt = 0; nt < 8; nt++) {
        mx0 = fmaxf(mx0, fmaxf(sacc[nt][0], sacc[nt][1]));
        mx1 = fmaxf(mx1, fmaxf(sacc[nt][2], sacc[nt][3]));
    }
    mx0 = fmaxf(mx0, __shfl_xor_sync(FULL, mx0, 1));
    mx0 = fmaxf(mx0, __shfl_xor_sync(FULL, mx0, 2));
    mx1 = fmaxf(mx1, __shfl_xor_sync(FULL, mx1, 1));
    mx1 = fmaxf(mx1, __shfl_xor_sync(FULL, mx1, 2));

    float sum0 = 0.f, sum1 = 0.f;
    #pragma unroll
    for (int nt = 0; nt < 8; nt++) {
        float e0 = rna_tf32(__expf((sacc[nt][0] - mx0) * ATTN_SCALE));
        float e1 = rna_tf32(__expf((sacc[nt][1] - mx0) * ATTN_SCALE));
        float e2 = rna_tf32(__expf((sacc[nt][2] - mx1) * ATTN_SCALE));
        float e3 = rna_tf32(__expf((sacc[nt][3] - mx1) * ATTN_SCALE));
        sacc[nt][0] = e0; sacc[nt][1] = e1; sacc[nt][2] = e2; sacc[nt][3] = e3;
        sum0 += e0 + e1; sum1 += e2 + e3;
    }
    sum0 += __shfl_xor_sync(FULL, sum0, 1);
    sum0 += __shfl_xor_sync(FULL, sum0, 2);
    sum1 += __shfl_xor_sync(FULL, sum1, 1);
    sum1 += __shfl_xor_sync(FULL, sum1, 2);
    const float inv0 = 1.f / sum0, inv1 = 1.f / sum1;

    // ---- O = P V  (16x32 per warp); P fragment = permuted S registers ----
    float oacc[4][4];
    #pragma unroll
    for (int nt = 0; nt < 4; nt++)
        #pragma unroll
        for (int j = 0; j < 4; j++) oacc[nt][j] = 0.f;

    #pragma unroll
    for (int kt = 0; kt < 8; kt++) {
        uint32_t a[4];
        a[0] = __float_as_uint(sacc[kt][0]);
        a[1] = __float_as_uint(sacc[kt][2]);
        a[2] = __float_as_uint(sacc[kt][1]);
        a[3] = __float_as_uint(sacc[kt][3]);
        #pragma unroll
        for (int nt = 0; nt < 4; nt++) {
            uint32_t b0 = __float_as_uint(vs[kt * 8 + cq][nt * 8 + r4]);
            uint32_t b1 = __float_as_uint(vs[kt * 8 + cq + 4][nt * 8 + r4]);
            mma1688(oacc[nt], a, b0, b1);
        }
    }

    // ---- write O (rows = tokens row, row+8; cols = hd) ----
    float* og = g_att + base;
    const int T0 = row, T1 = row + 8;
    const size_t sp0 = (size_t)(T0 >> 3) * Wc + (T0 & 7);
    const size_t sp1 = (size_t)(T1 >> 3) * Wc + (T1 & 7);
    #pragma unroll
    for (int nt = 0; nt < 4; nt++) {
        int hd0 = nt * 8 + 2 * cq;
        size_t c0 = (size_t)hd0 * HWc, c1 = c0 + HWc;
        og[c0 + sp0] = rna_tf32(oacc[nt][0] * inv0);
        og[c1 + sp0] = rna_tf32(oacc[nt][1] * inv0);
        og[c0 + sp1] = rna_tf32(oacc[nt][2] * inv1);
        og[c1 + sp1] = rna_tf32(oacc[nt][3] * inv1);
    }
}

// ---------------- launch ----------------
extern "C" void kernel_launch(void* const* d_in, const int* in_sizes, int n_in,
                              void* d_out, int out_size) {
    const float* x    = (const float*)d_in[0];
    const float* gn_w = (const float*)d_in[1];
    const float* gn_b = (const float*)d_in[2];
    const float* q_w  = (const float*)d_in[3];
    const float* q_b  = (const float*)d_in[4];
    const float* k_w  = (const float*)d_in[5];
    const float* k_b  = (const float*)d_in[6];
    const float* v_w  = (const float*)d_in[7];
    const float* v_b  = (const float*)d_in[8];
    const float* o_w  = (const float*)d_in[9];
    const float* o_b  = (const float*)d_in[10];
    float* out = (float*)d_out;

    cudaFuncSetAttribute(mma_gemm_kernel<false>,
                         cudaFuncAttributeMaxDynamicSharedMemorySize, SM_TOTAL_B);
    cudaFuncSetAttribute(mma_gemm_kernel<true>,
                         cudaFuncAttributeMaxDynamicSharedMemorySize, SM_TOTAL_B);

    gn_stats_kernel<<<Bc * Gc, 1024>>>(x);
    effw_kernel<<<Bc * 768, 256>>>(q_w, k_w, v_w, q_b, k_b, v_b, gn_w, gn_b);
    round_ow_kernel<<<64, 256>>>(o_w);

    dim3 gq(3, HWc / 128, Bc);
    mma_gemm_kernel<false><<<gq, 256, SM_TOTAL_B>>>(x, nullptr, nullptr, nullptr);

    dim3 ga(NWIN, NHc, Bc);
    attn_mma_kernel<<<ga, 128>>>();

    dim3 go(1, HWc / 128, Bc);
    mma_gemm_kernel<true><<<go, 256, SM_TOTAL_B>>>(nullptr, o_b, x, out);
}

// round 11
// speedup vs baseline: 2.4155x; 1.0574x over previous
#include <cuda_runtime.h>
#include <cstdint>

// ---------------- problem constants ----------------
#define Bc   4
#define Cc   256
#define Hc   256
#define Wc   256
#define HWc  65536
#define NHc  8
#define HDc  32
#define Pc   8
#define Gc   32
#define CPGc 8
#define NWIN 1024
#define EPSc 1e-6f
#define ATTN_SCALE 0.17677669529663689f
#define RSQRT2c 0.70710678118654757f

typedef unsigned long long ull;

// ---------------- device scratch (no cudaMalloc allowed) ----------------
__device__ float g_mean[Bc * Gc];
__device__ float g_rstd[Bc * Gc];
__device__ float g_effw[(size_t)Bc * 768 * 256];   // GN-folded qkv weights (tf32-rounded)
__device__ float g_effb[Bc * 768];                 // folded bias (fp32)
__device__ float g_owr[256 * 256];                 // o_w tf32-rounded
__device__ float g_qkv[(size_t)3 * Bc * Cc * HWc]; // [t][b][c][h][w]  (805 MB)
__device__ float g_att[(size_t)Bc * Cc * HWc];     // attention out (256 MB)

// ---------------- helpers ----------------
__device__ __forceinline__ float rna_tf32(float x) {
    uint32_t r;
    asm("cvt.rna.tf32.f32 %0, %1;" : "=r"(r) : "f"(x));
    return __uint_as_float(r);
}
__device__ __forceinline__ uint32_t smem_u32(const void* p) {
    uint32_t a;
    asm("{ .reg .u64 t; cvta.to.shared.u64 t, %1; cvt.u32.u64 %0, t; }" : "=r"(a) : "l"(p));
    return a;
}
__device__ __forceinline__ void cpasync16(uint32_t dst, const void* src) {
    asm volatile("cp.async.cg.shared.global [%0], [%1], 16;" :: "r"(dst), "l"(src) : "memory");
}
__device__ __forceinline__ void mma1688(float* d, const uint32_t* a, uint32_t b0, uint32_t b1) {
    asm volatile(
        "mma.sync.aligned.m16n8k8.row.col.f32.tf32.tf32.f32 "
        "{%0,%1,%2,%3}, {%4,%5,%6,%7}, {%8,%9}, {%0,%1,%2,%3};"
        : "+f"(d[0]), "+f"(d[1]), "+f"(d[2]), "+f"(d[3])
        : "r"(a[0]), "r"(a[1]), "r"(a[2]), "r"(a[3]), "r"(b0), "r"(b1));
}
__device__ __forceinline__ void ldmx4(uint32_t* r, uint32_t addr) {
    asm volatile("ldmatrix.sync.aligned.m8n8.x4.shared.b16 {%0,%1,%2,%3}, [%4];"
        : "=r"(r[0]), "=r"(r[1]), "=r"(r[2]), "=r"(r[3]) : "r"(addr));
}

// ---------------- kernel 1: GroupNorm statistics ----------------
__global__ __launch_bounds__(1024) void gn_stats_kernel(const float* __restrict__ x) {
    int bg = blockIdx.x;
    const float4* p = reinterpret_cast<const float4*>(x) + (size_t)bg * (CPGc * HWc / 4);
    float s = 0.f, ss = 0.f;
    const int n4 = CPGc * HWc / 4;
    for (int i = threadIdx.x; i < n4; i += blockDim.x) {
        float4 v = p[i];
        s  += (v.x + v.y) + (v.z + v.w);
        ss += (v.x * v.x + v.y * v.y) + (v.z * v.z + v.w * v.w);
    }
    const unsigned FULL = 0xffffffffu;
    #pragma unroll
    for (int o = 16; o; o >>= 1) { s += __shfl_down_sync(FULL, s, o); ss += __shfl_down_sync(FULL, ss, o); }
    __shared__ float w1[32], w2[32];
    int lane = threadIdx.x & 31, wid = threadIdx.x >> 5;
    if (lane == 0) { w1[wid] = s; w2[wid] = ss; }
    __syncthreads();
    if (wid == 0) {
        int nw = blockDim.x >> 5;
        s  = (lane < nw) ? w1[lane] : 0.f;
        ss = (lane < nw) ? w2[lane] : 0.f;
        #pragma unroll
        for (int o = 16; o; o >>= 1) { s += __shfl_down_sync(FULL, s, o); ss += __shfl_down_sync(FULL, ss, o); }
        if (lane == 0) {
            const float invN = 1.f / (float)(CPGc * HWc);
            float mu  = s * invN;
            float var = ss * invN - mu * mu;
            g_mean[bg] = mu;
            g_rstd[bg] = rsqrtf(var + EPSc);
        }
    }
}

// ---------------- kernel 2: fold GN into qkv weights (tf32-rounded) ----------------
__global__ __launch_bounds__(256) void effw_kernel(
    const float* __restrict__ qw, const float* __restrict__ kw, const float* __restrict__ vw,
    const float* __restrict__ qb, const float* __restrict__ kb, const float* __restrict__ vb,
    const float* __restrict__ gnw, const float* __restrict__ gnb)
{
    int bo = blockIdx.x;
    int b = bo / 768, o = bo % 768;
    int t = o >> 8, oc = o & 255;
    const float* Wm   = (t == 0) ? qw : ((t == 1) ? kw : vw);
    const float* bias = (t == 0) ? qb : ((t == 1) ? kb : vb);
    int c = threadIdx.x;
    float w  = Wm[oc * 256 + c];
    int g    = c >> 3;
    float rs = g_rstd[b * Gc + g];
    float mu = g_mean[b * Gc + g];
    float sC = rs * gnw[c];
    float tC = gnb[c] - mu * sC;
    g_effw[(size_t)bo * 256 + c] = rna_tf32(w * sC);

    float v = w * tC;
    const unsigned FULL = 0xffffffffu;
    #pragma unroll
    for (int off = 16; off; off >>= 1) v += __shfl_down_sync(FULL, v, off);
    __shared__ float ws[8];
    int lane = c & 31, wid = c >> 5;
    if (lane == 0) ws[wid] = v;
    __syncthreads();
    if (c == 0) {
        float sum = 0.f;
        #pragma unroll
        for (int i = 0; i < 8; i++) sum += ws[i];
        g_effb[bo] = sum + bias[oc];
    }
}

__global__ __launch_bounds__(256) void round_ow_kernel(const float* __restrict__ ow) {
    int j = blockIdx.x * blockDim.x + threadIdx.x; // 16384 float4s
    float4 v = ((const float4*)ow)[j];
    v.x = rna_tf32(v.x); v.y = rna_tf32(v.y);
    v.z = rna_tf32(v.z); v.w = rna_tf32(v.w);
    ((float4*)g_owr)[j] = v;
}

// ---------------- kernels 3 & 5: tf32 mma.sync GEMM ----------------
// C[n][m] = sum_k A[k][m] * W[n][k]  (A m-contiguous). CTA tile 128m x 256n, BK=32.
// 8 warps: warp_m = wid&1 (2), warp_n = wid>>1 (4); warp tile 64x64.
// smem floats per stage: A[32][136] = 4352, B[256][36] = 9216 -> 13568 words, 3 stages.
// A fragments register double-buffered at ks granularity; B frags via ldmatrix.
#define ASTG 4352
#define STGW 13568
#define SM_TOTAL_B (3 * STGW * 4) // 162816 bytes
#define NKI 8

template <bool OCONV>
__global__ void __launch_bounds__(256)
mma_gemm_kernel(const float* __restrict__ Ain, const float* __restrict__ biasin,
                const float* __restrict__ resid, float* __restrict__ outp)
{
    extern __shared__ float sm[];
    const uint32_t sbase = smem_u32(sm);
    const int tid = threadIdx.x, lane = tid & 31, wid = tid >> 5;
    const int warp_m = wid & 1, warp_n = wid >> 1;
    const int ny = blockIdx.x;
    const size_t mbase = (size_t)blockIdx.y * 128;
    const int b = blockIdx.z;

    const float* Ag = (OCONV ? g_att : Ain) + (size_t)b * Cc * HWc + mbase;
    const float* Wg = OCONV ? g_owr : (g_effw + ((size_t)b * 768 + ny * 256) * 256);

    float acc[4][8][4];
    #pragma unroll
    for (int i = 0; i < 4; i++)
        #pragma unroll
        for (int j = 0; j < 8; j++)
            #pragma unroll
            for (int l = 0; l < 4; l++) acc[i][j][l] = 0.f;

    auto issue = [&](int kt, int s) {
        const float* Asrc = Ag + (size_t)kt * 32 * HWc;
        uint32_t Ad = sbase + (uint32_t)(s * STGW) * 4u;
        #pragma unroll
        for (int it = 0; it < 4; it++) {
            int lin = it * 256 + tid;          // 0..1023
            int k = lin >> 5, m4 = (lin & 31) << 2;
            cpasync16(Ad + (uint32_t)(k * 136 + m4) * 4u, Asrc + (size_t)k * HWc + m4);
        }
        const float* Bsrc = Wg + kt * 32;
        uint32_t Bd = sbase + (uint32_t)(s * STGW + ASTG) * 4u;
        #pragma unroll
        for (int it = 0; it < 8; it++) {
            int lin = it * 256 + tid;          // 0..2047
            int n = lin >> 3, k4 = (lin & 7) << 2;
            cpasync16(Bd + (uint32_t)(n * 36 + k4) * 4u, Bsrc + (size_t)n * 256 + k4);
        }
        asm volatile("cp.async.commit_group;" ::: "memory");
    };

    issue(0, 0);
    issue(1, 1);

    const int r = lane >> 2, c = lane & 3;
    const uint32_t boff = ((uint32_t)((lane >> 3) & 1) * 8 + (lane & 7)) * 36 + ((lane >> 4) << 2);

    #pragma unroll 1
    for (int kt = 0; kt < NKI; kt++) {
        const int cur = kt % 3;
        if (kt == NKI - 1) asm volatile("cp.async.wait_group 0;" ::: "memory");
        else               asm volatile("cp.async.wait_group 1;" ::: "memory");
        __syncthreads();
        if (kt + 2 < NKI) issue(kt + 2, (kt + 2) % 3);

        const float* As = sm + cur * STGW;
        const uint32_t Bsu = sbase + (uint32_t)(cur * STGW + ASTG) * 4u
                           + (uint32_t)(warp_n * 64 * 36) * 4u;

        uint32_t af[2][4][4];
        auto lda = [&](int ks, uint32_t (&a)[4][4]) {
            const int kb = ks * 8;
            #pragma unroll
            for (int mt = 0; mt < 4; mt++) {
                int m = warp_m * 64 + mt * 16 + r;
                a[mt][0] = __float_as_uint(As[(kb + c) * 136 + m]);
                a[mt][1] = __float_as_uint(As[(kb + c) * 136 + m + 8]);
                a[mt][2] = __float_as_uint(As[(kb + c + 4) * 136 + m]);
                a[mt][3] = __float_as_uint(As[(kb + c + 4) * 136 + m + 8]);
            }
        };
        lda(0, af[0]);
        #pragma unroll
        for (int ks = 0; ks < 4; ks++) {
            if (ks < 3) lda(ks + 1, af[(ks + 1) & 1]);
            const int kb = ks * 8;
            #pragma unroll
            for (int g = 0; g < 4; g++) {
                uint32_t bf[4];
                ldmx4(bf, Bsu + (uint32_t)(g * 16 * 36 + kb + boff) * 4u);
                #pragma unroll
                for (int mt = 0; mt < 4; mt++) {
                    mma1688(acc[mt][2 * g],     af[ks & 1][mt], bf[0], bf[2]);
                    mma1688(acc[mt][2 * g + 1], af[ks & 1][mt], bf[1], bf[3]);
                }
            }
        }
    }

    // ---------------- epilogue ----------------
    const float* bptr = OCONV ? biasin : (g_effb + b * 768 + ny * 256);
    #pragma unroll
    for (int nt = 0; nt < 8; nt++) {
        int nloc = warp_n * 64 + nt * 8 + 2 * (lane & 3);
        float b0v = bptr[nloc], b1v = bptr[nloc + 1];
        #pragma unroll
        for (int mt = 0; mt < 4; mt++) {
            size_t mg = mbase + warp_m * 64 + mt * 16 + (lane >> 2);
            if (OCONV) {
                size_t o0 = ((size_t)b * Cc + nloc) * HWc + mg;
                size_t o1 = o0 + HWc;
                outp[o0]     = (acc[mt][nt][0] + b0v + resid[o0]) * RSQRT2c;
                outp[o1]     = (acc[mt][nt][1] + b1v + resid[o1]) * RSQRT2c;
                outp[o0 + 8] = (acc[mt][nt][2] + b0v + resid[o0 + 8]) * RSQRT2c;
                outp[o1 + 8] = (acc[mt][nt][3] + b1v + resid[o1 + 8]) * RSQRT2c;
            } else {
                size_t o0 = ((size_t)(ny * Bc + b) * Cc + nloc) * HWc + mg;
                size_t o1 = o0 + HWc;
                g_qkv[o0]     = acc[mt][nt][0] + b0v;
                g_qkv[o1]     = acc[mt][nt][1] + b1v;
                g_qkv[o0 + 8] = acc[mt][nt][2] + b0v;
                g_qkv[o1 + 8] = acc[mt][nt][3] + b1v;
            }
        }
    }
}

// ---------------- kernel 4: windowed attention via tf32 mma ----------------
// Block = 128 threads (4 warps) per (window, head, batch).
// q,v staged via cp.async float4 into [hd][tok] smem; k via LDG4 + permuted STS.
// O bounced through smem [tok][hd] (stride 34) then float4-coalesced STG.
#define QK_STR 72
#define OS_STR 34
__global__ __launch_bounds__(128) void attn_mma_kernel() {
    const int win = blockIdx.x, head = blockIdx.y, b = blockIdx.z;
    const int hpi = win >> 5, wpi = win & 31;

    __shared__ float qs[HDc][QK_STR];  // [hd][tok]  (reused as os[tok][hd] stride 34)
    __shared__ float ks[HDc][QK_STR];  // [hd][permuted tok]
    __shared__ float vs[HDc][QK_STR];  // [hd][tok]

    const int tid = threadIdx.x, lane = tid & 31, wid = tid >> 5;
    const size_t TSTR = (size_t)Bc * Cc * HWc;
    const size_t base = ((size_t)b * Cc + head * HDc) * HWc
                      + (size_t)(hpi * Pc) * Wc + wpi * Pc;
    const float* qg = g_qkv + base;
    const float* kg = g_qkv + TSTR + base;
    const float* vg = g_qkv + 2 * TSTR + base;

    const uint32_t qsb = smem_u32(&qs[0][0]);
    const uint32_t vsb = smem_u32(&vs[0][0]);
    float* ks0 = &ks[0][0];

    #pragma unroll
    for (int it = 0; it < 4; it++) {
        int lin = it * 128 + tid;          // 0..511
        int hd = lin >> 4, row = (lin >> 1) & 7, c4 = (lin & 1) << 2;
        size_t goff = (size_t)hd * HWc + (size_t)row * Wc + c4;
        uint32_t soff = (uint32_t)(hd * QK_STR + row * 8 + c4) * 4u;
        cpasync16(qsb + soff, qg + goff);
        cpasync16(vsb + soff, vg + goff);
        float4 kv = *(const float4*)(kg + goff);
        int kb = hd * QK_STR + row * 8 + (c4 >> 2);   // permuted: col = 2u + (c4>>2)
        ks0[kb + 0] = kv.x;
        ks0[kb + 2] = kv.y;
        ks0[kb + 4] = kv.z;
        ks0[kb + 6] = kv.w;
    }
    asm volatile("cp.async.commit_group;" ::: "memory");
    asm volatile("cp.async.wait_group 0;" ::: "memory");
    __syncthreads();

    const int r4 = lane >> 2, cq = lane & 3;
    const int row = wid * 16 + r4;

    // ---- S = Q K^T  (16x64 per warp) ----
    float sacc[8][4];
    #pragma unroll
    for (int nt = 0; nt < 8; nt++)
        #pragma unroll
        for (int j = 0; j < 4; j++) sacc[nt][j] = 0.f;

    #pragma unroll
    for (int kt = 0; kt < 4; kt++) {
        uint32_t a[4];
        a[0] = __float_as_uint(qs[kt * 8 + cq][row]);
        a[1] = __float_as_uint(qs[kt * 8 + cq][row + 8]);
        a[2] = __float_as_uint(qs[kt * 8 + cq + 4][row]);
        a[3] = __float_as_uint(qs[kt * 8 + cq + 4][row + 8]);
        #pragma unroll
        for (int nt = 0; nt < 8; nt++) {
            uint32_t b0 = __float_as_uint(ks[kt * 8 + cq][nt * 8 + r4]);
            uint32_t b1 = __float_as_uint(ks[kt * 8 + cq + 4][nt * 8 + r4]);
            mma1688(sacc[nt], a, b0, b1);
        }
    }

    // ---- softmax over the 64 columns (rows row and row+8 per thread) ----
    const unsigned FULL = 0xffffffffu;
    float mx0 = -3.0e38f, mx1 = -3.0e38f;
    #pragma unroll
    for (int nt = 0; nt < 8; nt++) {
        mx0 = fmaxf(mx0, fmaxf(sacc[nt][0], sacc[nt][1]));
        mx1 = fmaxf(mx1, fmaxf(sacc[nt][2], sacc[nt][3]));
    }
    mx0 = fmaxf(mx0, __shfl_xor_sync(FULL, mx0, 1));
    mx0 = fmaxf(mx0, __shfl_xor_sync(FULL, mx0, 2));
    mx1 = fmaxf(mx1, __shfl_xor_sync(FULL, mx1, 1));
    mx1 = fmaxf(mx1, __shfl_xor_sync(FULL, mx1, 2));

    float sum0 = 0.f, sum1 = 0.f;
    #pragma unroll
    for (int nt = 0; nt < 8; nt++) {
        float e0 = __expf((sacc[nt][0] - mx0) * ATTN_SCALE);
        float e1 = __expf((sacc[nt][1] - mx0) * ATTN_SCALE);
        float e2 = __expf((sacc[nt][2] - mx1) * ATTN_SCALE);
        float e3 = __expf((sacc[nt][3] - mx1) * ATTN_SCALE);
        sacc[nt][0] = e0; sacc[nt][1] = e1; sacc[nt][2] = e2; sacc[nt][3] = e3;
        sum0 += e0 + e1; sum1 += e2 + e3;
    }
    sum0 += __shfl_xor_sync(FULL, sum0, 1);
    sum0 += __shfl_xor_sync(FULL, sum0, 2);
    sum1 += __shfl_xor_sync(FULL, sum1, 1);
    sum1 += __shfl_xor_sync(FULL, sum1, 2);
    const float inv0 = 1.f / sum0, inv1 = 1.f / sum1;

    // ---- O = P V  (16x32 per warp); P fragment = permuted S registers ----
    float oacc[4][4];
    #pragma unroll
    for (int nt = 0; nt < 4; nt++)
        #pragma unroll
        for (int j = 0; j < 4; j++) oacc[nt][j] = 0.f;

    #pragma unroll
    for (int kt = 0; kt < 8; kt++) {
        uint32_t a[4];
        a[0] = __float_as_uint(sacc[kt][0]);
        a[1] = __float_as_uint(sacc[kt][2]);
        a[2] = __float_as_uint(sacc[kt][1]);
        a[3] = __float_as_uint(sacc[kt][3]);
        #pragma unroll
        for (int nt = 0; nt < 4; nt++) {
            uint32_t b0 = __float_as_uint(vs[nt * 8 + r4][kt * 8 + cq]);
            uint32_t b1 = __float_as_uint(vs[nt * 8 + r4][kt * 8 + cq + 4]);
            mma1688(oacc[nt], a, b0, b1);
        }
    }

    // ---- bounce O through smem (reuse qs region) then coalesced float4 STG ----
    __syncthreads();                       // all warps done reading qs
    float* os = &qs[0][0];                 // os[tok*34 + hd]
    const int T0 = row, T1 = row + 8;
    #pragma unroll
    for (int nt = 0; nt < 4; nt++) {
        int hd0 = nt * 8 + 2 * cq;
        *(float2*)(os + T0 * OS_STR + hd0) = make_float2(oacc[nt][0] * inv0, oacc[nt][1] * inv0);
        *(float2*)(os + T1 * OS_STR + hd0) = make_float2(oacc[nt][2] * inv1, oacc[nt][3] * inv1);
    }
    __syncthreads();

    float* og = g_att + base;
    #pragma unroll
    for (int it = 0; it < 4; it++) {
        int lin = it * 128 + tid;
        int hd = lin >> 4, rw = (lin >> 1) & 7, c4 = (lin & 1) << 2;
        int tb = rw * 8 + c4;
        float4 o;
        o.x = os[(tb + 0) * OS_STR + hd];
        o.y = os[(tb + 1) * OS_STR + hd];
        o.z = os[(tb + 2) * OS_STR + hd];
        o.w = os[(tb + 3) * OS_STR + hd];
        *(float4*)(og + (size_t)hd * HWc + (size_t)rw * Wc + c4) = o;
    }
}

// ---------------- launch ----------------
extern "C" void kernel_launch(void* const* d_in, const int* in_sizes, int n_in,
                              void* d_out, int out_size) {
    const float* x    = (const float*)d_in[0];
    const float* gn_w = (const float*)d_in[1];
    const float* gn_b = (const float*)d_in[2];
    const float* q_w  = (const float*)d_in[3];
    const float* q_b  = (const float*)d_in[4];
    const float* k_w  = (const float*)d_in[5];
    const float* k_b  = (const float*)d_in[6];
    const float* v_w  = (const float*)d_in[7];
    const float* v_b  = (const float*)d_in[8];
    const float* o_w  = (const float*)d_in[9];
    const float* o_b  = (const float*)d_in[10];
    float* out = (float*)d_out;

    cudaFuncSetAttribute(mma_gemm_kernel<false>,
                         cudaFuncAttributeMaxDynamicSharedMemorySize, SM_TOTAL_B);
    cudaFuncSetAttribute(mma_gemm_kernel<true>,
                         cudaFuncAttributeMaxDynamicSharedMemorySize, SM_TOTAL_B);

    gn_stats_kernel<<<Bc * Gc, 1024>>>(x);
    effw_kernel<<<Bc * 768, 256>>>(q_w, k_w, v_w, q_b, k_b, v_b, gn_w, gn_b);
    round_ow_kernel<<<64, 256>>>(o_w);

    dim3 gq(3, HWc / 128, Bc);
    mma_gemm_kernel<false><<<gq, 256, SM_TOTAL_B>>>(x, nullptr, nullptr, nullptr);

    dim3 ga(NWIN, NHc, Bc);
    attn_mma_kernel<<<ga, 128>>>();

    dim3 go(1, HWc / 128, Bc);
    mma_gemm_kernel<true><<<go, 256, SM_TOTAL_B>>>(nullptr, o_b, x, out);
}